// round 3
// baseline (speedup 1.0000x reference)
#include <cuda_runtime.h>

#define T_STEPS 50
#define BATCH   256
#define NS      64
#define NC      32
#define NN      96
#define NTHR    512

typedef unsigned long long ull;

// Global scratch for gains (forward pass replays them).
__device__ float g_K[(size_t)T_STEPS * BATCH * NC * NS];   // [t][b][32][64]
__device__ float g_k[(size_t)T_STEPS * BATCH * NC];        // [t][b][32]

// ---- shared memory layout (floats) ----
#define OFF_V    0                      // V carry, 64 x 65 (padded, symmetric)
#define OFF_F    (OFF_V   + 64*65)      // F tile,  64 x 96
#define OFF_Q    (OFF_F   + 64*96)      // Q, 96 x 96 (lower triangle valid)
#define OFF_WU   (OFF_Q   + 96*96)      // union: W(64x96) | K(32x64)+U(64x65)
#define OFF_K    (OFF_WU)
#define OFF_U    (OFF_WU  + 2048)
#define OFF_L    (OFF_WU  + 6208)       // Cholesky workspace, 32 x 33
#define OFF_ID   (OFF_L   + 32*33)      // inv diag, 32
#define OFF_v    (OFF_ID  + 32)         // v carry, 64
#define OFF_q    (OFF_v   + 64)         // q, 96
#define OFF_xut  (OFF_q   + 96)         // xut, 96
#define OFF_kv   (OFF_xut + 96)         // k vec, 32
#define OFF_x    (OFF_kv  + 32)         // fwd x, 64
#define OFF_dx   (OFF_x   + 64)         // fwd dx, 64
#define OFF_nu   (OFF_dx  + 64)         // fwd new_u, 32
#define SMEM_FLOATS (OFF_nu + 32)
#define SMEM_BYTES  (SMEM_FLOATS * 4)

// ---- packed fp32x2 helpers (SASS FFMA2 path) ----
__device__ __forceinline__ ull pk2(float lo, float hi) {
    ull r; asm("mov.b64 %0, {%1, %2};" : "=l"(r) : "f"(lo), "f"(hi)); return r;
}
__device__ __forceinline__ ull dup2(float x) { return pk2(x, x); }
__device__ __forceinline__ void upk2(float& lo, float& hi, ull v) {
    asm("mov.b64 {%0, %1}, %2;" : "=f"(lo), "=f"(hi) : "l"(v));
}
__device__ __forceinline__ void fma2(ull& d, ull a, ull b) {
    asm("fma.rn.f32x2 %0, %2, %3, %1;" : "=l"(d) : "l"(d), "l"(a), "l"(b));
}

__global__ __launch_bounds__(NTHR, 2)
void lqr_kernel(const float* __restrict__ x_init,
                const float* __restrict__ Cg,
                const float* __restrict__ cg,
                const float* __restrict__ Fg,
                const float* __restrict__ cxg,
                const float* __restrict__ cug,
                float* __restrict__ out)
{
    extern __shared__ float sm[];
    const int b   = blockIdx.x;
    const int tid = threadIdx.x;

    float* sV  = sm + OFF_V;
    float* sF  = sm + OFF_F;
    float* sQ  = sm + OFF_Q;
    float* sW  = sm + OFF_WU;
    float* sK  = sm + OFF_K;
    float* sU  = sm + OFF_U;
    float* sL  = sm + OFF_L;
    float* sid = sm + OFF_ID;
    float* sv  = sm + OFF_v;
    float* sq  = sm + OFF_q;
    float* sxu = sm + OFF_xut;
    float* skv = sm + OFF_kv;
    float* sx  = sm + OFF_x;
    float* sdx = sm + OFF_dx;
    float* snu = sm + OFF_nu;

    const int rb = tid >> 4, cb = tid & 15;   // 32 x 16 grid

    // Phase-2 job map: 3x4 tiles over 96x96, lower blocks (3bi+2 >= 4bj): 408 jobs.
    int p2bi = -1, p2bj = 0;
    {
        int idx = tid;
        #pragma unroll
        for (int r = 0; r < 32; ++r) {
            int cnt = (3 * r + 2) / 4 + 1;
            if (idx < cnt && p2bi < 0) { p2bi = r; p2bj = idx; }
            if (p2bi < 0) idx -= cnt;
        }
    }
    const bool p2a = (p2bi >= 0);

    // Vn job map: 2x4 tiles over 64x64, lower blocks (2bi+1 >= 4bj): 272 jobs.
    int vnbi = -1, vnbj = 0;
    {
        int idx = tid;
        #pragma unroll
        for (int r = 0; r < 32; ++r) {
            int cnt = (2 * r + 1) / 4 + 1;
            if (idx < cnt && vnbi < 0) { vnbi = r; vnbj = idx; }
            if (vnbi < 0) idx -= cnt;
        }
    }
    const bool vna = (vnbi >= 0);

    // ---------------- init carries + first F tile ----------------
    for (int i = tid; i < 64 * 65; i += NTHR) sV[i] = 0.f;
    if (tid < NS) sv[tid] = 0.f;
    {
        const float* Fsrc = Fg + ((size_t)(T_STEPS - 1) * BATCH + b) * (NS * NN);
        for (int i = tid; i < NS * NN; i += NTHR) sF[i] = Fsrc[i];
    }
    __syncthreads();

    // ================= BACKWARD RICCATI SCAN =================
    for (int t = T_STEPS - 1; t >= 0; --t) {
        const size_t tb = (size_t)t * BATCH + b;

        // xut (consumed by q phase two barriers later)
        if (tid < NS)       sxu[tid] = cxg[tb * NS + tid];
        else if (tid < NN)  sxu[tid] = cug[tb * NC + (tid - NS)];

        // ---- Phase 1: W = V @ F  (64x96, inner 64), 2x6 tiles, FFMA2 ----
        {
            const int i0 = rb * 2, j0 = cb * 6;
            ull acc[2][3];
            #pragma unroll
            for (int u = 0; u < 2; ++u)
                #pragma unroll
                for (int p = 0; p < 3; ++p) acc[u][p] = 0ull;
            #pragma unroll 8
            for (int a = 0; a < 64; ++a) {
                ull bv[3];
                #pragma unroll
                for (int p = 0; p < 3; ++p)
                    bv[p] = *reinterpret_cast<const ull*>(&sF[a * 96 + j0 + 2 * p]);
                ull a0 = dup2(sV[a * 65 + i0]);       // V symmetric: row<->col
                ull a1 = dup2(sV[a * 65 + i0 + 1]);
                #pragma unroll
                for (int p = 0; p < 3; ++p) { fma2(acc[0][p], a0, bv[p]);
                                              fma2(acc[1][p], a1, bv[p]); }
            }
            #pragma unroll
            for (int u = 0; u < 2; ++u)
                #pragma unroll
                for (int p = 0; p < 3; ++p)
                    *reinterpret_cast<ull*>(&sW[(i0 + u) * 96 + j0 + 2 * p]) = acc[u][p];
        }
        __syncthreads();

        // ---- Phase 2: lower triangle of Q = C + F^T W, 3x4 tiles, FFMA2 ----
        if (p2a) {
            const int i0 = p2bi * 3, j0 = p2bj * 4;
            ull acc[3][2];
            #pragma unroll
            for (int m = 0; m < 3; ++m) { acc[m][0] = 0ull; acc[m][1] = 0ull; }
            #pragma unroll 8
            for (int a = 0; a < 64; ++a) {
                float4 wb = *reinterpret_cast<const float4*>(&sW[a * 96 + j0]);
                ull w0 = pk2(wb.x, wb.y), w1 = pk2(wb.z, wb.w);
                ull f0 = dup2(sF[a * 96 + i0]);
                ull f1 = dup2(sF[a * 96 + i0 + 1]);
                ull f2 = dup2(sF[a * 96 + i0 + 2]);
                fma2(acc[0][0], f0, w0); fma2(acc[0][1], f0, w1);
                fma2(acc[1][0], f1, w0); fma2(acc[1][1], f1, w1);
                fma2(acc[2][0], f2, w0); fma2(acc[2][1], f2, w1);
            }
            const float* Crow = Cg + tb * (NN * NN);
            #pragma unroll
            for (int m = 0; m < 3; ++m) {
                float r0, r1, r2, r3;
                upk2(r0, r1, acc[m][0]); upk2(r2, r3, acc[m][1]);
                float4 cv = *reinterpret_cast<const float4*>(&Crow[(i0 + m) * 96 + j0]);
                float4 o = make_float4(r0 + cv.x, r1 + cv.y, r2 + cv.z, r3 + cv.w);
                *reinterpret_cast<float4*>(&sQ[(i0 + m) * 96 + j0]) = o;
            }
        }
        __syncthreads();

        // ---- q phase (tid<96) | stage Quu into 33-stride buffer (tid 128..255) ----
        if (tid < NN) {
            const float* Crow = Cg + tb * (NN * NN) + (size_t)tid * NN;
            float s = cg[tb * NN + tid];
            #pragma unroll 8
            for (int j = 0; j < NN; ++j) s += Crow[j] * sxu[j];
            float s2 = 0.f;
            #pragma unroll 8
            for (int a = 0; a < NS; ++a) s2 += sF[a * 96 + tid] * sv[a];
            sq[tid] = s + s2;
        } else if (tid >= 128 && tid < 256) {
            const int i = tid - 128;          // 128 threads, 8 elems each
            const int u = i >> 2;             // row 0..31
            const int c0 = (i & 3) * 8;       // col block
            float4 a0 = *reinterpret_cast<const float4*>(&sQ[(64 + u) * 96 + 64 + c0]);
            float4 a1 = *reinterpret_cast<const float4*>(&sQ[(64 + u) * 96 + 64 + c0 + 4]);
            sL[u * 33 + c0 + 0] = a0.x; sL[u * 33 + c0 + 1] = a0.y;
            sL[u * 33 + c0 + 2] = a0.z; sL[u * 33 + c0 + 3] = a0.w;
            sL[u * 33 + c0 + 4] = a1.x; sL[u * 33 + c0 + 5] = a1.y;
            sL[u * 33 + c0 + 6] = a1.z; sL[u * 33 + c0 + 7] = a1.w;
        }
        __syncthreads();

        // ---- Cholesky of Q_uu in-place in sL (warp 0) | prefetch next F ----
        if ((tid >> 5) == 0) {
            const int r = tid & 31;
            float Lr[32];
            #pragma unroll
            for (int kk = 0; kk < 32; ++kk) Lr[kk] = sL[r * 33 + kk];
            #pragma unroll
            for (int j = 0; j < 32; ++j) {
                float s = Lr[j];
                #pragma unroll
                for (int kk = 0; kk < j; ++kk) s -= Lr[kk] * sL[j * 33 + kk];
                float d = sqrtf(__shfl_sync(0xffffffffu, s, j));
                float val = (r == j) ? d : s / d;
                Lr[j] = val;
                if (r >= j) sL[r * 33 + j] = val;
                if (r == j) sid[j] = 1.0f / d;
                __syncwarp();
            }
        } else if (t > 0) {
            const float* Fsrc = Fg + ((size_t)(t - 1) * BATCH + b) * (NS * NN);
            for (int i = tid - 32; i < NS * NN; i += (NTHR - 32)) sF[i] = Fsrc[i];
        }
        __syncthreads();

        // ---- triangular solves: Quu y = rhs ; K = -y (64 cols), k = -y ----
        if (tid < 65) {
            float y[32];
            #pragma unroll
            for (int r2 = 0; r2 < 32; ++r2)
                y[r2] = (tid < 64) ? sQ[(64 + r2) * 96 + tid] : sq[64 + r2];
            #pragma unroll
            for (int j = 0; j < 32; ++j) {               // L y' = rhs
                float s = y[j];
                #pragma unroll
                for (int kk = 0; kk < j; ++kk) s -= sL[j * 33 + kk] * y[kk];
                y[j] = s * sid[j];
            }
            #pragma unroll
            for (int j = 31; j >= 0; --j) {              // L^T z = y'
                float s = y[j];
                #pragma unroll
                for (int kk = j + 1; kk < 32; ++kk) s -= sL[kk * 33 + j] * y[kk];
                y[j] = s * sid[j];
            }
            if (tid < 64) {
                #pragma unroll
                for (int r2 = 0; r2 < 32; ++r2) sK[r2 * 64 + tid] = -y[r2];
            } else {
                #pragma unroll
                for (int r2 = 0; r2 < 32; ++r2) skv[r2] = -y[r2];
            }
        }
        __syncthreads();

        // ---- U = Q_xu @ K = Q_ux^T @ K  (64x64, inner 32), 2x4 tiles, FFMA2 ----
        {
            const int i0 = rb * 2, j0 = cb * 4;
            ull acc[2][2];
            acc[0][0] = acc[0][1] = acc[1][0] = acc[1][1] = 0ull;
            #pragma unroll 8
            for (int r = 0; r < 32; ++r) {
                float4 kb = *reinterpret_cast<const float4*>(&sK[r * 64 + j0]);
                ull k0 = pk2(kb.x, kb.y), k1 = pk2(kb.z, kb.w);
                ull q0 = dup2(sQ[(64 + r) * 96 + i0]);
                ull q1 = dup2(sQ[(64 + r) * 96 + i0 + 1]);
                fma2(acc[0][0], q0, k0); fma2(acc[0][1], q0, k1);
                fma2(acc[1][0], q1, k0); fma2(acc[1][1], q1, k1);
            }
            #pragma unroll
            for (int u = 0; u < 2; ++u) {
                float v0, v1, v2, v3;
                upk2(v0, v1, acc[u][0]); upk2(v2, v3, acc[u][1]);
                sU[(i0 + u) * 65 + j0 + 0] = v0; sU[(i0 + u) * 65 + j0 + 1] = v1;
                sU[(i0 + u) * 65 + j0 + 2] = v2; sU[(i0 + u) * 65 + j0 + 3] = v3;
            }
        }
        // v_new = q_x + Q_xu @ k  (Q_ux column access, conflict-free)
        if (tid >= 64 && tid < 128) {
            const int i = tid - 64;
            float s = sq[i];
            #pragma unroll
            for (int r = 0; r < 32; ++r) s += sQ[(64 + r) * 96 + i] * skv[r];
            sv[i] = s;
        }
        // spill gains for forward pass
        if (tid >= 256) {
            float* gK = g_K + tb * (NC * NS);
            for (int i = tid - 256; i < NC * NS; i += 256) gK[i] = sK[i];
        }
        if (tid >= 224 && tid < 256) g_k[tb * NC + (tid - 224)] = skv[tid - 224];
        __syncthreads();

        // ---- Vn lower triangle + mirror: Vn = Q_xx + sym(U) ----
        if (vna) {
            const int i0 = vnbi * 2, j0 = vnbj * 4;
            #pragma unroll
            for (int u = 0; u < 2; ++u)
                #pragma unroll
                for (int v = 0; v < 4; ++v) {
                    const int i = i0 + u, j = j0 + v;
                    if (i >= j) {
                        float val = sQ[i * 96 + j]
                                  + 0.5f * (sU[i * 65 + j] + sU[j * 65 + i]);
                        sV[i * 65 + j] = val;
                        sV[j * 65 + i] = val;
                    }
                }
        }
        __syncthreads();
    }

    // ================= FORWARD ROLLOUT =================
    if (tid < NS) { sx[tid] = x_init[(size_t)b * NS + tid]; sdx[tid] = 0.f; }
    __syncthreads();

    for (int t = 0; t < T_STEPS; ++t) {
        const size_t tb = (size_t)t * BATCH + b;
        {
            const float* gK = g_K + tb * (NC * NS);
            for (int i = tid; i < NC * NS; i += NTHR) sK[i] = gK[i];
            const float* Fsrc = Fg + tb * (size_t)(NS * NN);
            for (int i = tid; i < NS * NN; i += NTHR) sF[i] = Fsrc[i];
        }
        __syncthreads();

        if (tid < NC) {   // new_u = K dx + u + k
            float s = g_k[tb * NC + tid] + cug[tb * NC + tid];
            #pragma unroll
            for (int j = 0; j < NS; ++j) {
                int jj = (j + tid) & 63;                 // bank-skew
                s += sK[tid * 64 + jj] * sdx[jj];
            }
            snu[tid] = s;
            out[(size_t)T_STEPS * BATCH * NS + tb * NC + tid] = s;
        }
        if (tid >= 64 && tid < 128) {                    // new_x[t] = x_t
            int i = tid - 64;
            out[tb * NS + i] = sx[i];
        }
        __syncthreads();

        if (tid < NS)       sxu[tid] = sx[tid];
        else if (tid < NN)  sxu[tid] = snu[tid - NS];
        __syncthreads();

        if (tid < NS) {   // x_next = F @ [x; new_u]
            float s = 0.f;
            #pragma unroll
            for (int j = 0; j < NN; ++j) {
                int jj = j + tid; if (jj >= NN) jj -= NN; // bank-skew
                s += sF[tid * 96 + jj] * sxu[jj];
            }
            float xr = (t < T_STEPS - 1)
                     ? cxg[((size_t)(t + 1) * BATCH + b) * NS + tid] : 0.f;
            sx[tid]  = s;
            sdx[tid] = s - xr;
        }
        __syncthreads();
    }
}

extern "C" void kernel_launch(void* const* d_in, const int* in_sizes, int n_in,
                              void* d_out, int out_size)
{
    const float* x_init = (const float*)d_in[0];
    const float* C      = (const float*)d_in[1];
    const float* c      = (const float*)d_in[2];
    const float* F      = (const float*)d_in[3];
    const float* cx     = (const float*)d_in[4];
    const float* cu     = (const float*)d_in[5];

    cudaFuncSetAttribute(lqr_kernel,
                         cudaFuncAttributeMaxDynamicSharedMemorySize, SMEM_BYTES);
    lqr_kernel<<<BATCH, NTHR, SMEM_BYTES>>>(x_init, C, c, F, cx, cu, (float*)d_out);
}

// round 4
// speedup vs baseline: 1.4117x; 1.4117x over previous
#include <cuda_runtime.h>

#define T_STEPS 50
#define BATCH   256
#define NS      64
#define NC      32
#define NN      96
#define NTHR    256

typedef unsigned long long ull;

__device__ float g_K[(size_t)T_STEPS * BATCH * NC * NS];   // [t][b][32][64]
__device__ float g_k[(size_t)T_STEPS * BATCH * NC];        // [t][b][32]

// ---- shared memory layout (floats) ----
#define OFF_V    0                      // V carry, 64 x 65 (symmetric)
#define OFF_F    (OFF_V   + 64*65)      // F tile,  64 x 96
#define OFF_Q    (OFF_F   + 64*96)      // Q, 96 x 96 FULL (mirrored)
#define OFF_WU   (OFF_Q   + 96*96)      // union: W(64x96) | K(32x64)+U(64x65)
#define OFF_K    (OFF_WU)
#define OFF_U    (OFF_WU  + 2048)
#define OFF_L    (OFF_WU  + 6208)       // Cholesky workspace, 32 x 33
#define OFF_ID   (OFF_L   + 32*33)      // inv diag, 32
#define OFF_v    (OFF_ID  + 32)         // v carry, 64
#define OFF_q    (OFF_v   + 64)         // q, 96
#define OFF_xut  (OFF_q   + 96)         // xut, 96
#define OFF_kv   (OFF_xut + 96)         // k vec, 32
#define OFF_x    (OFF_kv  + 32)         // fwd x, 64
#define OFF_dx   (OFF_x   + 64)         // fwd dx, 64
#define OFF_nu   (OFF_dx  + 64)         // fwd new_u, 32
#define OFF_t    (OFF_nu  + 32)         // t = v - W@xut, 64
#define SMEM_FLOATS (OFF_t + 64)
#define SMEM_BYTES  (SMEM_FLOATS * 4)

// ---- packed fp32x2 helpers (SASS FFMA2 path) ----
__device__ __forceinline__ ull pk2(float lo, float hi) {
    ull r; asm("mov.b64 %0, {%1, %2};" : "=l"(r) : "f"(lo), "f"(hi)); return r;
}
__device__ __forceinline__ ull dup2(float x) { return pk2(x, x); }
__device__ __forceinline__ void upk2(float& lo, float& hi, ull v) {
    asm("mov.b64 {%0, %1}, %2;" : "=f"(lo), "=f"(hi) : "l"(v));
}
__device__ __forceinline__ void fma2(ull& d, ull a, ull b) {
    asm("fma.rn.f32x2 %0, %2, %3, %1;" : "=l"(d) : "l"(d), "l"(a), "l"(b));
}

__global__ __launch_bounds__(NTHR, 2)
void lqr_kernel(const float* __restrict__ x_init,
                const float* __restrict__ Cg,
                const float* __restrict__ cg,
                const float* __restrict__ Fg,
                const float* __restrict__ cxg,
                const float* __restrict__ cug,
                float* __restrict__ out)
{
    extern __shared__ float sm[];
    const int b   = blockIdx.x;
    const int tid = threadIdx.x;

    float* sV  = sm + OFF_V;
    float* sF  = sm + OFF_F;
    float* sQ  = sm + OFF_Q;
    float* sW  = sm + OFF_WU;
    float* sK  = sm + OFF_K;
    float* sU  = sm + OFF_U;
    float* sL  = sm + OFF_L;
    float* sid = sm + OFF_ID;
    float* sv  = sm + OFF_v;
    float* sq  = sm + OFF_q;
    float* sxu = sm + OFF_xut;
    float* skv = sm + OFF_kv;
    float* sx  = sm + OFF_x;
    float* sdx = sm + OFF_dx;
    float* snu = sm + OFF_nu;
    float* st  = sm + OFF_t;

    const int ty = tid >> 4, tx = tid & 15;

    // Phase-2 job map: 6x4 tiles over 96x96, lower blocks (6bi+5 >= 4bj): 208 jobs.
    int p2bi = -1, p2bj = 0;
    {
        int idx = tid;
        #pragma unroll
        for (int r = 0; r < 16; ++r) {
            int cnt = (6 * r + 5) / 4 + 1;
            if (idx < cnt && p2bi < 0) { p2bi = r; p2bj = idx; }
            if (p2bi < 0) idx -= cnt;
        }
    }
    const bool p2a = (p2bi >= 0);

    // ---------------- init carries + first F tile ----------------
    for (int i = tid; i < 64 * 65; i += NTHR) sV[i] = 0.f;
    if (tid < NS) sv[tid] = 0.f;
    {
        const float* Fsrc = Fg + ((size_t)(T_STEPS - 1) * BATCH + b) * (NS * NN);
        for (int i = tid; i < NS * NN; i += NTHR) sF[i] = Fsrc[i];
    }
    __syncthreads();

    // ================= BACKWARD RICCATI SCAN =================
    for (int t = T_STEPS - 1; t >= 0; --t) {
        const size_t tb = (size_t)t * BATCH + b;

        // xut (consumed by slot A / B)
        if (tid < NS)       sxu[tid] = cxg[tb * NS + tid];
        else if (tid < NN)  sxu[tid] = cug[tb * NC + (tid - NS)];

        // ---- Phase 1: W = V @ F  (64x96, inner 64), 4x6 tiles, FFMA2 ----
        {
            const int i0 = ty * 4, j0 = tx * 6;
            ull acc[4][3];
            #pragma unroll
            for (int u = 0; u < 4; ++u)
                #pragma unroll
                for (int p = 0; p < 3; ++p) acc[u][p] = 0ull;
            #pragma unroll 4
            for (int a = 0; a < 64; ++a) {
                ull bv[3];
                #pragma unroll
                for (int p = 0; p < 3; ++p)
                    bv[p] = *reinterpret_cast<const ull*>(&sF[a * 96 + j0 + 2 * p]);
                float av[4];
                #pragma unroll
                for (int u = 0; u < 4; ++u) av[u] = sV[a * 65 + i0 + u]; // V symmetric
                #pragma unroll
                for (int u = 0; u < 4; ++u) {
                    ull ad = dup2(av[u]);
                    #pragma unroll
                    for (int p = 0; p < 3; ++p) fma2(acc[u][p], ad, bv[p]);
                }
            }
            #pragma unroll
            for (int u = 0; u < 4; ++u)
                #pragma unroll
                for (int p = 0; p < 3; ++p)
                    *reinterpret_cast<ull*>(&sW[(i0 + u) * 96 + j0 + 2 * p]) = acc[u][p];
        }
        __syncthreads();

        // ---- Phase 2: Q = C + F^T W, lower 6x4 tiles + mirror to full ----
        if (p2a) {
            const int i0 = p2bi * 6, j0 = p2bj * 4;
            const float* Crow = Cg + tb * (NN * NN);
            // hoisted C loads (overlap DRAM latency with the FFMA loop)
            float4 cL[6];
            #pragma unroll
            for (int r = 0; r < 6; ++r)
                cL[r] = *reinterpret_cast<const float4*>(&Crow[(i0 + r) * 96 + j0]);

            ull acc[3][4];
            #pragma unroll
            for (int m = 0; m < 3; ++m)
                #pragma unroll
                for (int v = 0; v < 4; ++v) acc[m][v] = 0ull;
            #pragma unroll 4
            for (int a = 0; a < 64; ++a) {
                ull am[3];
                #pragma unroll
                for (int m = 0; m < 3; ++m)
                    am[m] = *reinterpret_cast<const ull*>(&sF[a * 96 + i0 + 2 * m]);
                float4 wb = *reinterpret_cast<const float4*>(&sW[a * 96 + j0]);
                ull wd[4] = { dup2(wb.x), dup2(wb.y), dup2(wb.z), dup2(wb.w) };
                #pragma unroll
                for (int m = 0; m < 3; ++m)
                    #pragma unroll
                    for (int v = 0; v < 4; ++v) fma2(acc[m][v], am[m], wd[v]);
            }
            #pragma unroll
            for (int m = 0; m < 3; ++m) {
                float r0[4], r1[4];
                #pragma unroll
                for (int v = 0; v < 4; ++v) upk2(r0[v], r1[v], acc[m][v]);
                const float* c0 = &cL[2 * m].x;
                const float* c1 = &cL[2 * m + 1].x;
                #pragma unroll
                for (int v = 0; v < 4; ++v) {
                    const int i = i0 + 2 * m, j = j0 + v;
                    float val = r0[v] + c0[v];
                    if (i >= j) sQ[i * 96 + j] = val;     // lower direct
                    if (i >  j) sQ[j * 96 + i] = val;     // mirror (unique writer)
                }
                #pragma unroll
                for (int v = 0; v < 4; ++v) {
                    const int i = i0 + 2 * m + 1, j = j0 + v;
                    float val = r1[v] + c1[v];
                    if (i >= j) sQ[i * 96 + j] = val;
                    if (i >  j) sQ[j * 96 + i] = val;
                }
            }
        }
        __syncthreads();

        // ---- Slot A: t = v - W@xut (tid<64) | stage Quu into sL (tid 128..255) ----
        if (tid < 64) {
            const int a = tid;
            float s0 = 0.f, s1 = 0.f, s2 = 0.f, s3 = 0.f;
            #pragma unroll 8
            for (int j = 0; j < 96; j += 4) {
                int j0i = j + a;     if (j0i >= 96) j0i -= 96;
                int j1i = j + 1 + a; if (j1i >= 96) j1i -= 96;
                int j2i = j + 2 + a; if (j2i >= 96) j2i -= 96;
                int j3i = j + 3 + a; if (j3i >= 96) j3i -= 96;
                s0 += sW[a * 96 + j0i] * sxu[j0i];
                s1 += sW[a * 96 + j1i] * sxu[j1i];
                s2 += sW[a * 96 + j2i] * sxu[j2i];
                s3 += sW[a * 96 + j3i] * sxu[j3i];
            }
            st[a] = sv[a] - (s0 + s1) - (s2 + s3);
        } else if (tid >= 128) {
            const int i = tid - 128;          // 128 threads, 8 elems each
            const int u = i >> 2;             // row 0..31
            const int c0 = (i & 3) * 8;       // col block
            float4 a0 = *reinterpret_cast<const float4*>(&sQ[(64 + u) * 96 + 64 + c0]);
            float4 a1 = *reinterpret_cast<const float4*>(&sQ[(64 + u) * 96 + 64 + c0 + 4]);
            sL[u * 33 + c0 + 0] = a0.x; sL[u * 33 + c0 + 1] = a0.y;
            sL[u * 33 + c0 + 2] = a0.z; sL[u * 33 + c0 + 3] = a0.w;
            sL[u * 33 + c0 + 4] = a1.x; sL[u * 33 + c0 + 5] = a1.y;
            sL[u * 33 + c0 + 6] = a1.z; sL[u * 33 + c0 + 7] = a1.w;
        }
        __syncthreads();

        // ---- Slot B: q = c + Q@xut + F^T t (tid<96) | Cholesky (warp 4) ----
        if (tid < NN) {
            const int i = tid;
            float cval = cg[tb * NN + i];              // hoisted global load
            float s0 = 0.f, s1 = 0.f, s2 = 0.f, s3 = 0.f;
            #pragma unroll 8
            for (int j = 0; j < 96; j += 4) {           // rotated, conflict-free
                int j0i = j + i;     if (j0i >= 96) j0i -= 96;
                int j1i = j + 1 + i; if (j1i >= 96) j1i -= 96;
                int j2i = j + 2 + i; if (j2i >= 96) j2i -= 96;
                int j3i = j + 3 + i; if (j3i >= 96) j3i -= 96;
                s0 += sQ[i * 96 + j0i] * sxu[j0i];
                s1 += sQ[i * 96 + j1i] * sxu[j1i];
                s2 += sQ[i * 96 + j2i] * sxu[j2i];
                s3 += sQ[i * 96 + j3i] * sxu[j3i];
            }
            float f0 = 0.f, f1 = 0.f;
            #pragma unroll 8
            for (int a = 0; a < 64; a += 2) {           // column walk, own bank
                f0 += sF[a * 96 + i] * st[a];
                f1 += sF[(a + 1) * 96 + i] * st[a + 1];
            }
            sq[i] = cval + (s0 + s1) + (s2 + s3) + (f0 + f1);
        } else if (tid >= 128 && tid < 160) {
            const int r = tid - 128;
            float Lr[32];
            #pragma unroll
            for (int kk = 0; kk < 32; ++kk) Lr[kk] = sL[r * 33 + kk];
            #pragma unroll
            for (int j = 0; j < 32; ++j) {
                float s = Lr[j];
                #pragma unroll
                for (int kk = 0; kk < j; ++kk) s -= Lr[kk] * sL[j * 33 + kk];
                float d = sqrtf(__shfl_sync(0xffffffffu, s, j));
                float val = (r == j) ? d : s / d;
                Lr[j] = val;
                if (r >= j) sL[r * 33 + j] = val;
                if (r == j) sid[j] = 1.0f / d;
                __syncwarp();
            }
        }
        __syncthreads();

        // ---- Solve (tid<65) | prefetch next F (tid>=96) ----
        if (tid < 65) {
            float y[32];
            #pragma unroll
            for (int r2 = 0; r2 < 32; ++r2)
                y[r2] = (tid < 64) ? sQ[(64 + r2) * 96 + tid] : sq[64 + r2];
            #pragma unroll
            for (int j = 0; j < 32; ++j) {               // L y' = rhs
                float s = y[j];
                #pragma unroll
                for (int kk = 0; kk < j; ++kk) s -= sL[j * 33 + kk] * y[kk];
                y[j] = s * sid[j];
            }
            #pragma unroll
            for (int j = 31; j >= 0; --j) {              // L^T z = y'
                float s = y[j];
                #pragma unroll
                for (int kk = j + 1; kk < 32; ++kk) s -= sL[kk * 33 + j] * y[kk];
                y[j] = s * sid[j];
            }
            if (tid < 64) {
                #pragma unroll
                for (int r2 = 0; r2 < 32; ++r2) sK[r2 * 64 + tid] = -y[r2];
            } else {
                #pragma unroll
                for (int r2 = 0; r2 < 32; ++r2) skv[r2] = -y[r2];
            }
        } else if (tid >= 96 && t > 0) {
            const float* Fsrc = Fg + ((size_t)(t - 1) * BATCH + b) * (NS * NN);
            for (int i = tid - 96; i < NS * NN; i += 160) sF[i] = Fsrc[i];
        }
        __syncthreads();

        // ---- U = Q_xu @ K (64x64, inner 32), 4x4 tiles, FFMA2 ----
        {
            const int i0 = ty * 4, j0 = tx * 4;
            ull acc[4][2];
            #pragma unroll
            for (int u = 0; u < 4; ++u) { acc[u][0] = 0ull; acc[u][1] = 0ull; }
            #pragma unroll 4
            for (int r = 0; r < 32; ++r) {
                float4 qa = *reinterpret_cast<const float4*>(&sQ[(64 + r) * 96 + i0]);
                float4 kb = *reinterpret_cast<const float4*>(&sK[r * 64 + j0]);
                ull kb2[2] = { pk2(kb.x, kb.y), pk2(kb.z, kb.w) };
                ull q0 = dup2(qa.x), q1 = dup2(qa.y), q2 = dup2(qa.z), q3 = dup2(qa.w);
                fma2(acc[0][0], q0, kb2[0]); fma2(acc[0][1], q0, kb2[1]);
                fma2(acc[1][0], q1, kb2[0]); fma2(acc[1][1], q1, kb2[1]);
                fma2(acc[2][0], q2, kb2[0]); fma2(acc[2][1], q2, kb2[1]);
                fma2(acc[3][0], q3, kb2[0]); fma2(acc[3][1], q3, kb2[1]);
            }
            #pragma unroll
            for (int u = 0; u < 4; ++u) {
                float v0, v1, v2, v3;
                upk2(v0, v1, acc[u][0]); upk2(v2, v3, acc[u][1]);
                sU[(i0 + u) * 65 + j0 + 0] = v0; sU[(i0 + u) * 65 + j0 + 1] = v1;
                sU[(i0 + u) * 65 + j0 + 2] = v2; sU[(i0 + u) * 65 + j0 + 3] = v3;
            }
        }
        // v_new = q_x + Q_xu @ k  (column walk, conflict-free)
        if (tid < 64) {
            float s = sq[tid];
            #pragma unroll
            for (int r = 0; r < 32; ++r) s += sQ[(64 + r) * 96 + tid] * skv[r];
            sv[tid] = s;
        }
        // spill gains for forward pass
        {
            float* gK = g_K + tb * (NC * NS);
            for (int i = tid; i < NC * NS; i += NTHR) gK[i] = sK[i];
            if (tid < NC) g_k[tb * NC + tid] = skv[tid];
        }
        __syncthreads();

        // ---- Vn lower triangle + mirror: Vn = Q_xx + sym(U) ----
        if (ty >= tx) {
            const int i0 = ty * 4, j0 = tx * 4;
            #pragma unroll
            for (int u = 0; u < 4; ++u)
                #pragma unroll
                for (int v = 0; v < 4; ++v) {
                    const int i = i0 + u, j = j0 + v;
                    if (i >= j) {
                        float val = sQ[i * 96 + j]
                                  + 0.5f * (sU[i * 65 + j] + sU[j * 65 + i]);
                        sV[i * 65 + j] = val;
                        sV[j * 65 + i] = val;
                    }
                }
        }
        __syncthreads();
    }

    // ================= FORWARD ROLLOUT =================
    if (tid < NS) { sx[tid] = x_init[(size_t)b * NS + tid]; sdx[tid] = 0.f; }
    __syncthreads();

    for (int t = 0; t < T_STEPS; ++t) {
        const size_t tb = (size_t)t * BATCH + b;
        {
            const float* gK = g_K + tb * (NC * NS);
            for (int i = tid; i < NC * NS; i += NTHR) sK[i] = gK[i];
            const float* Fsrc = Fg + tb * (size_t)(NS * NN);
            for (int i = tid; i < NS * NN; i += NTHR) sF[i] = Fsrc[i];
        }
        __syncthreads();

        if (tid < NC) {   // new_u = K dx + u + k
            float s = g_k[tb * NC + tid] + cug[tb * NC + tid];
            #pragma unroll
            for (int j = 0; j < NS; ++j) {
                int jj = (j + tid) & 63;                 // bank-skew
                s += sK[tid * 64 + jj] * sdx[jj];
            }
            snu[tid] = s;
            out[(size_t)T_STEPS * BATCH * NS + tb * NC + tid] = s;
        }
        if (tid >= 64 && tid < 128) {                    // new_x[t] = x_t
            int i = tid - 64;
            out[tb * NS + i] = sx[i];
        }
        __syncthreads();

        if (tid < NS)       sxu[tid] = sx[tid];
        else if (tid < NN)  sxu[tid] = snu[tid - NS];
        __syncthreads();

        if (tid < NS) {   // x_next = F @ [x; new_u]
            float s = 0.f;
            #pragma unroll
            for (int j = 0; j < NN; ++j) {
                int jj = j + tid; if (jj >= NN) jj -= NN; // bank-skew
                s += sF[tid * 96 + jj] * sxu[jj];
            }
            float xr = (t < T_STEPS - 1)
                     ? cxg[((size_t)(t + 1) * BATCH + b) * NS + tid] : 0.f;
            sx[tid]  = s;
            sdx[tid] = s - xr;
        }
        __syncthreads();
    }
}

extern "C" void kernel_launch(void* const* d_in, const int* in_sizes, int n_in,
                              void* d_out, int out_size)
{
    const float* x_init = (const float*)d_in[0];
    const float* C      = (const float*)d_in[1];
    const float* c      = (const float*)d_in[2];
    const float* F      = (const float*)d_in[3];
    const float* cx     = (const float*)d_in[4];
    const float* cu     = (const float*)d_in[5];

    cudaFuncSetAttribute(lqr_kernel,
                         cudaFuncAttributeMaxDynamicSharedMemorySize, SMEM_BYTES);
    lqr_kernel<<<BATCH, NTHR, SMEM_BYTES>>>(x_init, C, c, F, cx, cu, (float*)d_out);
}

// round 5
// speedup vs baseline: 1.7045x; 1.2074x over previous
#include <cuda_runtime.h>

#define T_STEPS 50
#define BATCH   256
#define NS      64
#define NC      32
#define NN      96
#define NTHR    256

typedef unsigned long long ull;

__device__ float g_K[(size_t)T_STEPS * BATCH * NC * NS];   // [t][b][32][64]
__device__ float g_k[(size_t)T_STEPS * BATCH * NC];        // [t][b][32]

// ---- shared memory layout (floats) ----
#define OFF_V    0                       // V carry, 64 x 68 (symmetric)
#define OFF_F    (OFF_V  + 64*68)        // F tile, 64 x 96
#define OFF_Q    (OFF_F  + 6144)         // Q, 96 x 96 FULL (mirrored)
#define OFF_WB   (OFF_Q  + 9216)         // W (64x96) -- dead after phase 2
#define OFF_L    (OFF_WB)                // Cholesky 32x33   (overlaps W)
#define OFF_LI   (OFF_L  + 1056)         // Linv 32x33       (overlaps W)
#define OFF_Z    (OFF_LI + 1056)         // Z 32x65          (overlaps W)
#define OFF_K    (OFF_Z  + 2080)         // K 32x64          (overlaps W tail)
#define OFF_v    (OFF_K  + 2048)         // v carry, 64
#define OFF_q    (OFF_v  + 64)           // q, 96
#define OFF_xu   (OFF_q  + 96)           // xut, 96
#define OFF_kv   (OFF_xu + 96)           // k vec, 32
#define OFF_T    (OFF_kv + 32)           // t = v - V z, 64
#define OFF_id   (OFF_T  + 64)           // inv diag, 32
#define OFF_zv   (OFF_id + 32)           // z = F xut, 64
#define OFF_FWD  (OFF_zv + 64)           // forward-pass arrays (480)
#define SMEM_FLOATS (OFF_FWD + 480)
#define SMEM_BYTES  (SMEM_FLOATS * 4)

// ---- packed fp32x2 helpers (SASS FFMA2 path) ----
__device__ __forceinline__ ull pk2(float lo, float hi) {
    ull r; asm("mov.b64 %0, {%1, %2};" : "=l"(r) : "f"(lo), "f"(hi)); return r;
}
__device__ __forceinline__ ull dup2(float x) { return pk2(x, x); }
__device__ __forceinline__ void upk2(float& lo, float& hi, ull v) {
    asm("mov.b64 {%0, %1}, %2;" : "=f"(lo), "=f"(hi) : "l"(v));
}
__device__ __forceinline__ void fma2(ull& d, ull a, ull b) {
    asm("fma.rn.f32x2 %0, %2, %3, %1;" : "=l"(d) : "l"(d), "l"(a), "l"(b));
}

__global__ __launch_bounds__(NTHR, 2)
void lqr_kernel(const float* __restrict__ x_init,
                const float* __restrict__ Cg,
                const float* __restrict__ cg,
                const float* __restrict__ Fg,
                const float* __restrict__ cxg,
                const float* __restrict__ cug,
                float* __restrict__ out)
{
    extern __shared__ float sm[];
    const int b   = blockIdx.x;
    const int tid = threadIdx.x;

    float* sV  = sm + OFF_V;
    float* sF  = sm + OFF_F;
    float* sQ  = sm + OFF_Q;
    float* sW  = sm + OFF_WB;
    float* sL  = sm + OFF_L;
    float* sLi = sm + OFF_LI;
    float* sZ  = sm + OFF_Z;
    float* sK  = sm + OFF_K;
    float* sv  = sm + OFF_v;
    float* sq  = sm + OFF_q;
    float* sxu = sm + OFF_xu;
    float* skv = sm + OFF_kv;
    float* st  = sm + OFF_T;
    float* sid = sm + OFF_id;
    float* sz  = sm + OFF_zv;

    const int ty = tid >> 4, tx = tid & 15;

    // Phase-2 job map: 6x4 tiles over 96x96, lower blocks (6bi+5>=4bj): 208 jobs.
    int p2bi = -1, p2bj = 0;
    {
        int idx = tid;
        #pragma unroll
        for (int r = 0; r < 16; ++r) {
            int cnt = (6 * r + 5) / 4 + 1;
            if (idx < cnt && p2bi < 0) { p2bi = r; p2bj = idx; }
            if (p2bi < 0) idx -= cnt;
        }
    }
    const bool p2a = (p2bi >= 0);

    // Phase-7 pair-tile map: 4x4 tiles on 64x64, (bi>=bj): 136 jobs.
    int u7bi = -1, u7bj = 0;
    {
        int idx = tid;
        #pragma unroll
        for (int r = 0; r < 16; ++r) {
            int cnt = r + 1;
            if (idx < cnt && u7bi < 0) { u7bi = r; u7bj = idx; }
            if (u7bi < 0) idx -= cnt;
        }
    }

    // ---------------- init ----------------
    for (int i = tid; i < 64 * 68; i += NTHR) sV[i] = 0.f;
    if (tid < NS) sv[tid] = 0.f;
    {
        const float* Fsrc = Fg + ((size_t)(T_STEPS - 1) * BATCH + b) * (NS * NN);
        for (int i = tid; i < NS * NN; i += NTHR) sF[i] = Fsrc[i];
    }
    __syncthreads();

    // ================= BACKWARD RICCATI SCAN =================
    for (int t = T_STEPS - 1; t >= 0; --t) {
        const size_t tb = (size_t)t * BATCH + b;

        // xut (first read in phase 2)
        if (tid < NS)       sxu[tid] = cxg[tb * NS + tid];
        else if (tid < NN)  sxu[tid] = cug[tb * NC + (tid - NS)];

        // ---- P1: W = V @ F (64x96, inner 64), 4x6 FFMA2 tiles ----
        {
            const int i0 = ty * 4, j0 = tx * 6;
            ull acc[4][3];
            #pragma unroll
            for (int u = 0; u < 4; ++u)
                #pragma unroll
                for (int p = 0; p < 3; ++p) acc[u][p] = 0ull;
            #pragma unroll 4
            for (int a = 0; a < 64; ++a) {
                ull bv[3];
                #pragma unroll
                for (int p = 0; p < 3; ++p)
                    bv[p] = *reinterpret_cast<const ull*>(&sF[a * 96 + j0 + 2 * p]);
                float4 av = *reinterpret_cast<const float4*>(&sV[a * 68 + i0]); // V sym
                ull a0 = dup2(av.x), a1 = dup2(av.y), a2 = dup2(av.z), a3 = dup2(av.w);
                #pragma unroll
                for (int p = 0; p < 3; ++p) {
                    fma2(acc[0][p], a0, bv[p]); fma2(acc[1][p], a1, bv[p]);
                    fma2(acc[2][p], a2, bv[p]); fma2(acc[3][p], a3, bv[p]);
                }
            }
            #pragma unroll
            for (int u = 0; u < 4; ++u)
                #pragma unroll
                for (int p = 0; p < 3; ++p)
                    *reinterpret_cast<ull*>(&sW[(i0 + u) * 96 + j0 + 2 * p]) = acc[u][p];
        }
        __syncthreads();

        // ---- P2: Q = C + F^T W (lower 6x4 + mirror) | z = F @ xut ----
        if (p2a) {
            const int i0 = p2bi * 6, j0 = p2bj * 4;
            const float* Crow = Cg + tb * (NN * NN);
            float4 cL[6];
            #pragma unroll
            for (int r = 0; r < 6; ++r)
                cL[r] = *reinterpret_cast<const float4*>(&Crow[(i0 + r) * 96 + j0]);

            ull acc[3][4];
            #pragma unroll
            for (int m = 0; m < 3; ++m)
                #pragma unroll
                for (int v = 0; v < 4; ++v) acc[m][v] = 0ull;
            #pragma unroll 4
            for (int a = 0; a < 64; ++a) {
                ull am[3];
                #pragma unroll
                for (int m = 0; m < 3; ++m)
                    am[m] = *reinterpret_cast<const ull*>(&sF[a * 96 + i0 + 2 * m]);
                float4 wb = *reinterpret_cast<const float4*>(&sW[a * 96 + j0]);
                ull wd[4] = { dup2(wb.x), dup2(wb.y), dup2(wb.z), dup2(wb.w) };
                #pragma unroll
                for (int m = 0; m < 3; ++m)
                    #pragma unroll
                    for (int v = 0; v < 4; ++v) fma2(acc[m][v], am[m], wd[v]);
            }
            #pragma unroll
            for (int m = 0; m < 3; ++m) {
                float r0[4], r1[4];
                #pragma unroll
                for (int v = 0; v < 4; ++v) upk2(r0[v], r1[v], acc[m][v]);
                const float* c0 = &cL[2 * m].x;
                const float* c1 = &cL[2 * m + 1].x;
                #pragma unroll
                for (int v = 0; v < 4; ++v) {
                    const int i = i0 + 2 * m, j = j0 + v;
                    float val = r0[v] + c0[v];
                    if (i >= j) sQ[i * 96 + j] = val;
                    if (i >  j) sQ[j * 96 + i] = val;
                }
                #pragma unroll
                for (int v = 0; v < 4; ++v) {
                    const int i = i0 + 2 * m + 1, j = j0 + v;
                    float val = r1[v] + c1[v];
                    if (i >= j) sQ[i * 96 + j] = val;
                    if (i >  j) sQ[j * 96 + i] = val;
                }
            }
        } else if (tid >= 208) {
            // z = F @ xut, outputs o and o+48 (o<16)
            #pragma unroll
            for (int rep = 0; rep < 2; ++rep) {
                int o = (tid - 208) + rep * 48;
                if (o < 64) {
                    int ro = (3 * o) % 96;
                    float s0 = 0.f, s1 = 0.f;
                    #pragma unroll 8
                    for (int j = 0; j < 96; j += 2) {
                        int j0i = j + ro;     if (j0i >= 96) j0i -= 96;
                        int j1i = j + 1 + ro; if (j1i >= 96) j1i -= 96;
                        s0 += sF[o * 96 + j0i] * sxu[j0i];
                        s1 += sF[o * 96 + j1i] * sxu[j1i];
                    }
                    sz[o] = s0 + s1;
                }
            }
        }
        __syncthreads();

        // ---- P3: qA = c + Q@xut (0-95) | t = v - V@z (96-159) | stage sL (160-255) ----
        if (tid < NN) {
            const int i = tid;
            float cval = cg[tb * NN + i];
            float s0 = 0.f, s1 = 0.f, s2 = 0.f, s3 = 0.f;
            #pragma unroll 8
            for (int j = 0; j < 96; j += 4) {
                int j0i = j + i;     if (j0i >= 96) j0i -= 96;
                int j1i = j + 1 + i; if (j1i >= 96) j1i -= 96;
                int j2i = j + 2 + i; if (j2i >= 96) j2i -= 96;
                int j3i = j + 3 + i; if (j3i >= 96) j3i -= 96;
                s0 += sQ[i * 96 + j0i] * sxu[j0i];
                s1 += sQ[i * 96 + j1i] * sxu[j1i];
                s2 += sQ[i * 96 + j2i] * sxu[j2i];
                s3 += sQ[i * 96 + j3i] * sxu[j3i];
            }
            sq[i] = cval + (s0 + s1) + (s2 + s3);
        } else if (tid < 160) {
            const int a = tid - 96;
            const int ra = (3 * a) & 63;
            float s0 = 0.f, s1 = 0.f;
            #pragma unroll 8
            for (int j = 0; j < 64; j += 2) {
                int j0i = (j + ra) & 63;
                int j1i = (j + 1 + ra) & 63;
                s0 += sV[a * 68 + j0i] * sz[j0i];
                s1 += sV[a * 68 + j1i] * sz[j1i];
            }
            st[a] = sv[a] - s0 - s1;
        } else {
            for (int idx = tid - 160; idx < 1024; idx += 96) {
                int u = idx >> 5, c = idx & 31;
                sL[u * 33 + c] = sQ[(64 + u) * 96 + 64 + c];
            }
        }
        __syncthreads();

        // ---- P4: q += F^T t (0-95) | Cholesky + Linv (warp 4: 128-159) ----
        if (tid < NN) {
            const int i = tid;
            float f0 = 0.f, f1 = 0.f;
            #pragma unroll 8
            for (int a = 0; a < 64; a += 2) {
                f0 += sF[a * 96 + i] * st[a];
                f1 += sF[(a + 1) * 96 + i] * st[a + 1];
            }
            sq[i] += f0 + f1;
        } else if (tid >= 128 && tid < 160) {
            const int r = tid - 128;
            float Lr[32];
            #pragma unroll
            for (int kk = 0; kk < 32; ++kk) Lr[kk] = sL[r * 33 + kk];
            #pragma unroll
            for (int j = 0; j < 32; ++j) {
                float s = Lr[j];
                #pragma unroll
                for (int kk = 0; kk < j; ++kk) s -= Lr[kk] * sL[j * 33 + kk];
                float d = sqrtf(__shfl_sync(0xffffffffu, s, j));
                float val = (r == j) ? d : s / d;
                Lr[j] = val;
                if (r >= j) sL[r * 33 + j] = val;
                if (r == j) sid[j] = 1.0f / d;
                __syncwarp();
            }
            // triangular inverse: lane r computes column r of Linv
            {
                float x[32];
                #pragma unroll
                for (int j = 0; j < 32; ++j) {
                    float s = (j == r) ? 1.0f : 0.0f;
                    #pragma unroll
                    for (int kk = 0; kk < j; ++kk) s -= sL[j * 33 + kk] * x[kk];
                    x[j] = (j < r) ? 0.0f : s * sid[j];
                    sLi[j * 33 + r] = x[j];
                }
            }
        }
        __syncthreads();

        // ---- P5: Z = Linv @ [Q_ux | q_u] (tid<130) | F-prefetch 1/2 (160-255) ----
        if (tid < 130) {
            const int c  = tid % 65;
            const int r0 = (tid / 65) * 16;
            float acc[16];
            #pragma unroll
            for (int rr = 0; rr < 16; ++rr) acc[rr] = 0.f;
            #pragma unroll 4
            for (int j = 0; j < 32; ++j) {
                float rv = (c < 64) ? sQ[(64 + j) * 96 + c] : sq[64 + j];
                #pragma unroll
                for (int rr = 0; rr < 16; ++rr)
                    acc[rr] += sLi[(r0 + rr) * 33 + j] * rv;
            }
            #pragma unroll
            for (int rr = 0; rr < 16; ++rr) sZ[(r0 + rr) * 65 + c] = acc[rr];
        } else if (tid >= 160 && t > 0) {
            const float4* Fsrc = reinterpret_cast<const float4*>(
                Fg + ((size_t)(t - 1) * BATCH + b) * (NS * NN));
            float4* Fd = reinterpret_cast<float4*>(sF);
            for (int i = tid - 160; i < 768; i += 96) Fd[i] = Fsrc[i];
        }
        __syncthreads();

        // ---- P6: K = -Linv^T @ Z -> sK,gK,skv,g_k | F-prefetch 2/2 ----
        if (tid < 130) {
            const int c  = tid % 65;
            const int r0 = (tid / 65) * 16;
            float acc[16];
            #pragma unroll
            for (int rr = 0; rr < 16; ++rr) acc[rr] = 0.f;
            #pragma unroll 4
            for (int j = 0; j < 32; ++j) {
                float zv = sZ[j * 65 + c];
                #pragma unroll
                for (int rr = 0; rr < 16; ++rr)
                    acc[rr] += sLi[j * 33 + r0 + rr] * zv;
            }
            if (c < 64) {
                float* gK = g_K + tb * (NC * NS);
                #pragma unroll
                for (int rr = 0; rr < 16; ++rr) {
                    float val = -acc[rr];
                    sK[(r0 + rr) * 64 + c] = val;
                    gK[(r0 + rr) * 64 + c] = val;
                }
            } else {
                #pragma unroll
                for (int rr = 0; rr < 16; ++rr) {
                    float val = -acc[rr];
                    skv[r0 + rr] = val;
                    g_k[tb * NC + r0 + rr] = val;
                }
            }
        } else if (tid >= 160 && t > 0) {
            const float4* Fsrc = reinterpret_cast<const float4*>(
                Fg + ((size_t)(t - 1) * BATCH + b) * (NS * NN));
            float4* Fd = reinterpret_cast<float4*>(sF);
            for (int i = 768 + (tid - 160); i < 1536; i += 96) Fd[i] = Fsrc[i];
        }
        __syncthreads();

        // ---- P7: Vn = Q_xx + sym(Q_xu K) via register pair-tiles | v_new ----
        if (u7bi >= 0) {
            const int i0 = u7bi * 4, j0 = u7bj * 4;
            if (u7bi == u7bj) {
                ull acc[4][2];
                #pragma unroll
                for (int u = 0; u < 4; ++u) { acc[u][0] = 0ull; acc[u][1] = 0ull; }
                #pragma unroll 4
                for (int r = 0; r < 32; ++r) {
                    float4 qa = *reinterpret_cast<const float4*>(&sQ[(64 + r) * 96 + i0]);
                    float4 kb = *reinterpret_cast<const float4*>(&sK[r * 64 + j0]);
                    ull k0 = pk2(kb.x, kb.y), k1 = pk2(kb.z, kb.w);
                    fma2(acc[0][0], dup2(qa.x), k0); fma2(acc[0][1], dup2(qa.x), k1);
                    fma2(acc[1][0], dup2(qa.y), k0); fma2(acc[1][1], dup2(qa.y), k1);
                    fma2(acc[2][0], dup2(qa.z), k0); fma2(acc[2][1], dup2(qa.z), k1);
                    fma2(acc[3][0], dup2(qa.w), k0); fma2(acc[3][1], dup2(qa.w), k1);
                }
                float U[4][4];
                #pragma unroll
                for (int u = 0; u < 4; ++u) {
                    upk2(U[u][0], U[u][1], acc[u][0]);
                    upk2(U[u][2], U[u][3], acc[u][1]);
                }
                #pragma unroll
                for (int u = 0; u < 4; ++u)
                    #pragma unroll
                    for (int v = 0; v < 4; ++v)
                        sV[(i0 + u) * 68 + j0 + v] =
                            sQ[(i0 + u) * 96 + j0 + v] + 0.5f * (U[u][v] + U[v][u]);
            } else {
                ull accA[4][2], accB[4][2];
                #pragma unroll
                for (int u = 0; u < 4; ++u) {
                    accA[u][0] = accA[u][1] = 0ull;
                    accB[u][0] = accB[u][1] = 0ull;
                }
                #pragma unroll 2
                for (int r = 0; r < 32; ++r) {
                    float4 qi = *reinterpret_cast<const float4*>(&sQ[(64 + r) * 96 + i0]);
                    float4 qj = *reinterpret_cast<const float4*>(&sQ[(64 + r) * 96 + j0]);
                    float4 ki = *reinterpret_cast<const float4*>(&sK[r * 64 + i0]);
                    float4 kj = *reinterpret_cast<const float4*>(&sK[r * 64 + j0]);
                    ull kj0 = pk2(kj.x, kj.y), kj1 = pk2(kj.z, kj.w);
                    ull ki0 = pk2(ki.x, ki.y), ki1 = pk2(ki.z, ki.w);
                    fma2(accA[0][0], dup2(qi.x), kj0); fma2(accA[0][1], dup2(qi.x), kj1);
                    fma2(accA[1][0], dup2(qi.y), kj0); fma2(accA[1][1], dup2(qi.y), kj1);
                    fma2(accA[2][0], dup2(qi.z), kj0); fma2(accA[2][1], dup2(qi.z), kj1);
                    fma2(accA[3][0], dup2(qi.w), kj0); fma2(accA[3][1], dup2(qi.w), kj1);
                    fma2(accB[0][0], dup2(qj.x), ki0); fma2(accB[0][1], dup2(qj.x), ki1);
                    fma2(accB[1][0], dup2(qj.y), ki0); fma2(accB[1][1], dup2(qj.y), ki1);
                    fma2(accB[2][0], dup2(qj.z), ki0); fma2(accB[2][1], dup2(qj.z), ki1);
                    fma2(accB[3][0], dup2(qj.w), ki0); fma2(accB[3][1], dup2(qj.w), ki1);
                }
                float A[4][4], B[4][4];
                #pragma unroll
                for (int u = 0; u < 4; ++u) {
                    upk2(A[u][0], A[u][1], accA[u][0]);
                    upk2(A[u][2], A[u][3], accA[u][1]);
                    upk2(B[u][0], B[u][1], accB[u][0]);
                    upk2(B[u][2], B[u][3], accB[u][1]);
                }
                #pragma unroll
                for (int u = 0; u < 4; ++u)
                    #pragma unroll
                    for (int v = 0; v < 4; ++v) {
                        float val = sQ[(i0 + u) * 96 + j0 + v]
                                  + 0.5f * (A[u][v] + B[v][u]);
                        sV[(i0 + u) * 68 + j0 + v] = val;
                        sV[(j0 + v) * 68 + i0 + u] = val;
                    }
            }
        } else if (tid >= 136 && tid < 200) {
            const int i = tid - 136;
            float s = sq[i];
            #pragma unroll
            for (int r = 0; r < 32; ++r) s += sQ[(64 + r) * 96 + i] * skv[r];
            sv[i] = s;
        }
        __syncthreads();
    }

    // ================= FORWARD ROLLOUT (double-buffered) =================
    float* fx  = sm + OFF_FWD;        // x, 2 x 64
    float* fdx = fx  + 128;           // dx, 64
    float* fnu = fdx + 64;            // new_u, 32
    float* fk  = fnu + 32;            // k, 2 x 32
    float* fu  = fk  + 64;            // u, 2 x 32
    float* fxr = fu  + 64;            // xr, 2 x 64
    float* KB[2] = { sK, sZ };
    float* FB[2] = { sF, sQ };

    // preload t=0 buffers
    {
        const float4* Ks = reinterpret_cast<const float4*>(g_K + (size_t)b * (NC * NS));
        float4* Kd = reinterpret_cast<float4*>(KB[0]);
        for (int i = tid; i < 512; i += NTHR) Kd[i] = Ks[i];
        const float4* Fs = reinterpret_cast<const float4*>(Fg + (size_t)b * (NS * NN));
        float4* Fd = reinterpret_cast<float4*>(FB[0]);
        for (int i = tid; i < 1536; i += NTHR) Fd[i] = Fs[i];
        if (tid < 32) {
            fk[tid] = g_k[(size_t)b * NC + tid];
            fu[tid] = cug[(size_t)b * NC + tid];
        } else if (tid < 96) {
            int i = tid - 32;
            fxr[i] = cxg[((size_t)BATCH + b) * NS + i];   // cx[1]
        } else if (tid < 160) {
            int i = tid - 96;
            fx[i]  = x_init[(size_t)b * NS + i];
            fdx[i] = 0.f;
        }
    }
    __syncthreads();

    for (int t = 0; t < T_STEPS; ++t) {
        const int cur = t & 1, nxt = cur ^ 1;
        const size_t tb = (size_t)t * BATCH + b;

        // Phase A: new_u (0-127, quad-split) | prefetch t+1 + x output (128-255)
        if (tid < 128) {
            const int o = tid >> 2, seg = tid & 3;
            const float* Kb = KB[cur] + o * 64 + seg * 16;
            const float* dx = fdx + seg * 16;
            float s = 0.f;
            #pragma unroll
            for (int j = 0; j < 16; ++j) s += Kb[j] * dx[j];
            s += __shfl_xor_sync(0xffffffffu, s, 1);
            s += __shfl_xor_sync(0xffffffffu, s, 2);
            if (seg == 0) {
                float nu = s + fk[cur * 32 + o] + fu[cur * 32 + o];
                fnu[o] = nu;
                out[(size_t)T_STEPS * BATCH * NS + tb * NC + o] = nu;
            }
        } else {
            const int idx = tid - 128;
            if (idx < 64) out[tb * NS + idx] = fx[cur * 64 + idx];
            if (t + 1 < T_STEPS) {
                const size_t tb2 = tb + BATCH;
                const float4* Ks = reinterpret_cast<const float4*>(g_K + tb2 * (NC * NS));
                float4* Kd = reinterpret_cast<float4*>(KB[nxt]);
                for (int i = idx; i < 512; i += 128) Kd[i] = Ks[i];
                const float4* Fs = reinterpret_cast<const float4*>(Fg + tb2 * (NS * NN));
                float4* Fd = reinterpret_cast<float4*>(FB[nxt]);
                for (int i = idx; i < 1536; i += 128) Fd[i] = Fs[i];
                if (idx < 32) {
                    fk[nxt * 32 + idx] = g_k[tb2 * NC + idx];
                    fu[nxt * 32 + idx] = cug[tb2 * NC + idx];
                } else if (idx < 96) {
                    int i = idx - 32;
                    fxr[nxt * 64 + i] = (t + 2 < T_STEPS)
                        ? cxg[(tb2 + BATCH) * NS + i] : 0.f;
                }
            }
        }
        __syncthreads();

        // Phase B: x_next = F @ [x; new_u] (all 256, quad-split 24)
        {
            const int o = tid >> 2, seg = tid & 3;
            const float* Fr = FB[cur] + o * 96 + seg * 24;
            float s = 0.f;
            #pragma unroll
            for (int j = 0; j < 24; ++j) {
                int jj = seg * 24 + j;
                float xv = (jj < 64) ? fx[cur * 64 + jj] : fnu[jj - 64];
                s += Fr[j] * xv;
            }
            s += __shfl_xor_sync(0xffffffffu, s, 1);
            s += __shfl_xor_sync(0xffffffffu, s, 2);
            if (seg == 0) {
                fx[nxt * 64 + o] = s;
                fdx[o] = s - fxr[cur * 64 + o];
            }
        }
        __syncthreads();
    }
}

extern "C" void kernel_launch(void* const* d_in, const int* in_sizes, int n_in,
                              void* d_out, int out_size)
{
    const float* x_init = (const float*)d_in[0];
    const float* C      = (const float*)d_in[1];
    const float* c      = (const float*)d_in[2];
    const float* F      = (const float*)d_in[3];
    const float* cx     = (const float*)d_in[4];
    const float* cu     = (const float*)d_in[5];

    cudaFuncSetAttribute(lqr_kernel,
                         cudaFuncAttributeMaxDynamicSharedMemorySize, SMEM_BYTES);
    lqr_kernel<<<BATCH, NTHR, SMEM_BYTES>>>(x_init, C, c, F, cx, cu, (float*)d_out);
}

// round 6
// speedup vs baseline: 1.7092x; 1.0028x over previous
#include <cuda_runtime.h>

#define T_STEPS 50
#define BATCH   256
#define NS      64
#define NC      32
#define NN      96
#define NTHR    256

typedef unsigned long long ull;

__device__ float g_K[(size_t)T_STEPS * BATCH * NC * NS];   // [t][b][32][64]
__device__ float g_k[(size_t)T_STEPS * BATCH * NC];        // [t][b][32]

// ---- shared memory layout (floats) ----
#define OFF_V    0                       // V carry, 64 x 68 (symmetric)
#define OFF_F    (OFF_V  + 64*68)        // F tile, 64 x 96
#define OFF_Q    (OFF_F  + 6144)         // Q, 96 x 96 FULL (mirrored)
#define OFF_WB   (OFF_Q  + 9216)         // W (64x96) -- dead after phase 2
#define OFF_L    (OFF_WB)                // Cholesky 32x33   (overlaps W)
#define OFF_LI   (OFF_L  + 1056)         // Linv 32x33       (overlaps W)
#define OFF_Z    (OFF_LI + 1056)         // Z 32x65          (overlaps W)
#define OFF_K    (OFF_Z  + 2080)         // K 32x64          (overlaps W tail)
#define OFF_v    (OFF_K  + 2048)         // v carry, 64
#define OFF_q    (OFF_v  + 64)           // q, 96
#define OFF_xu   (OFF_q  + 96)           // xut, 96
#define OFF_kv   (OFF_xu + 96)           // k vec, 32
#define OFF_T    (OFF_kv + 32)           // t = v - V z, 64
#define OFF_id   (OFF_T  + 64)           // inv diag, 32
#define OFF_zv   (OFF_id + 32)           // z = F xut, 64
#define OFF_FWD  (OFF_zv + 64)           // forward-pass arrays (480)
#define SMEM_FLOATS (OFF_FWD + 480)
#define SMEM_BYTES  (SMEM_FLOATS * 4)

// ---- packed fp32x2 helpers (SASS FFMA2 path) ----
__device__ __forceinline__ ull pk2(float lo, float hi) {
    ull r; asm("mov.b64 %0, {%1, %2};" : "=l"(r) : "f"(lo), "f"(hi)); return r;
}
__device__ __forceinline__ ull dup2(float x) { return pk2(x, x); }
__device__ __forceinline__ void upk2(float& lo, float& hi, ull v) {
    asm("mov.b64 {%0, %1}, %2;" : "=f"(lo), "=f"(hi) : "l"(v));
}
__device__ __forceinline__ void fma2(ull& d, ull a, ull b) {
    asm("fma.rn.f32x2 %0, %2, %3, %1;" : "=l"(d) : "l"(d), "l"(a), "l"(b));
}

__global__ __launch_bounds__(NTHR, 2)
void lqr_kernel(const float* __restrict__ x_init,
                const float* __restrict__ Cg,
                const float* __restrict__ cg,
                const float* __restrict__ Fg,
                const float* __restrict__ cxg,
                const float* __restrict__ cug,
                float* __restrict__ out)
{
    extern __shared__ float sm[];
    const int b   = blockIdx.x;
    const int tid = threadIdx.x;

    float* sV  = sm + OFF_V;
    float* sF  = sm + OFF_F;
    float* sQ  = sm + OFF_Q;
    float* sW  = sm + OFF_WB;
    float* sL  = sm + OFF_L;
    float* sLi = sm + OFF_LI;
    float* sZ  = sm + OFF_Z;
    float* sK  = sm + OFF_K;
    float* sv  = sm + OFF_v;
    float* sq  = sm + OFF_q;
    float* sxu = sm + OFF_xu;
    float* skv = sm + OFF_kv;
    float* st  = sm + OFF_T;
    float* sid = sm + OFF_id;
    float* sz  = sm + OFF_zv;

    // Phase-2 job map: 6x8 tiles over 96x96, lower blocks (6bi+5 >= 8bj): 108 jobs.
    int p2bi = -1, p2bj = 0;
    {
        int idx = tid;
        #pragma unroll
        for (int r = 0; r < 16; ++r) {
            int cnt = (6 * r + 5) / 8 + 1;
            if (idx < cnt && p2bi < 0) { p2bi = r; p2bj = idx; }
            if (p2bi < 0) idx -= cnt;
        }
    }
    const bool p2a = (p2bi >= 0);

    // Phase-7 pair-tile map: 4x4 tiles on 64x64, (bi>=bj): 136 jobs.
    int u7bi = -1, u7bj = 0;
    {
        int idx = tid;
        #pragma unroll
        for (int r = 0; r < 16; ++r) {
            int cnt = r + 1;
            if (idx < cnt && u7bi < 0) { u7bi = r; u7bj = idx; }
            if (u7bi < 0) idx -= cnt;
        }
    }

    // ---------------- init ----------------
    for (int i = tid; i < 64 * 68; i += NTHR) sV[i] = 0.f;
    if (tid < NS) sv[tid] = 0.f;
    {
        const float* Fsrc = Fg + ((size_t)(T_STEPS - 1) * BATCH + b) * (NS * NN);
        for (int i = tid; i < NS * NN; i += NTHR) sF[i] = Fsrc[i];
    }
    __syncthreads();

    // ================= BACKWARD RICCATI SCAN =================
    for (int t = T_STEPS - 1; t >= 0; --t) {
        const size_t tb = (size_t)t * BATCH + b;

        // ---- P1: W = V @ F (64x96, inner 64), 4x12 FFMA2 tiles (tid<128)
        //      | xut load + z = F @ xut (tid>=128) ----
        if (tid < 128) {
            const int i0 = (tid >> 3) * 4;      // 16 row-blocks
            const int j0 = (tid & 7) * 12;      // 8 col-blocks
            ull acc[4][6];
            #pragma unroll
            for (int u = 0; u < 4; ++u)
                #pragma unroll
                for (int p = 0; p < 6; ++p) acc[u][p] = 0ull;
            #pragma unroll 2
            for (int a = 0; a < 64; ++a) {
                float4 b0 = *reinterpret_cast<const float4*>(&sF[a * 96 + j0]);
                float4 b1 = *reinterpret_cast<const float4*>(&sF[a * 96 + j0 + 4]);
                float4 b2 = *reinterpret_cast<const float4*>(&sF[a * 96 + j0 + 8]);
                ull bv[6] = { pk2(b0.x, b0.y), pk2(b0.z, b0.w),
                              pk2(b1.x, b1.y), pk2(b1.z, b1.w),
                              pk2(b2.x, b2.y), pk2(b2.z, b2.w) };
                float4 av = *reinterpret_cast<const float4*>(&sV[a * 68 + i0]); // V sym
                ull a0 = dup2(av.x), a1 = dup2(av.y), a2 = dup2(av.z), a3 = dup2(av.w);
                #pragma unroll
                for (int p = 0; p < 6; ++p) {
                    fma2(acc[0][p], a0, bv[p]); fma2(acc[1][p], a1, bv[p]);
                    fma2(acc[2][p], a2, bv[p]); fma2(acc[3][p], a3, bv[p]);
                }
            }
            #pragma unroll
            for (int u = 0; u < 4; ++u)
                #pragma unroll
                for (int p = 0; p < 6; ++p)
                    *reinterpret_cast<ull*>(&sW[(i0 + u) * 96 + j0 + 2 * p]) = acc[u][p];
        } else {
            const int idx = tid - 128;
            if (idx < NS)            sxu[idx] = cxg[tb * NS + idx];
            else if (idx < NN)       sxu[idx] = cug[tb * NC + (idx - NS)];
            asm volatile("bar.sync 3, 128;" ::: "memory");   // warps 4-7 only
            if (idx < 64) {
                const int o = idx;
                int ro = (3 * o) % 96;
                float s0 = 0.f, s1 = 0.f;
                #pragma unroll 8
                for (int j = 0; j < 96; j += 2) {
                    int j0i = j + ro;     if (j0i >= 96) j0i -= 96;
                    int j1i = j + 1 + ro; if (j1i >= 96) j1i -= 96;
                    s0 += sF[o * 96 + j0i] * sxu[j0i];
                    s1 += sF[o * 96 + j1i] * sxu[j1i];
                }
                sz[o] = s0 + s1;
            } else {
                asm volatile("" ::: "memory");
            }
        }
        __syncthreads();

        // ---- P2: Q = C + F^T W (lower 6x8 tiles + mirror), 108 jobs ----
        if (p2a) {
            const int i0 = p2bi * 6, j0 = p2bj * 8;
            const float* Crow = Cg + tb * (NN * NN);
            float4 cL[6][2];
            #pragma unroll
            for (int r = 0; r < 6; ++r) {
                cL[r][0] = *reinterpret_cast<const float4*>(&Crow[(i0 + r) * 96 + j0]);
                cL[r][1] = *reinterpret_cast<const float4*>(&Crow[(i0 + r) * 96 + j0 + 4]);
            }
            ull acc[3][8];
            #pragma unroll
            for (int m = 0; m < 3; ++m)
                #pragma unroll
                for (int v = 0; v < 8; ++v) acc[m][v] = 0ull;
            #pragma unroll 2
            for (int a = 0; a < 64; ++a) {
                ull am[3];
                #pragma unroll
                for (int m = 0; m < 3; ++m)
                    am[m] = *reinterpret_cast<const ull*>(&sF[a * 96 + i0 + 2 * m]);
                float4 w0 = *reinterpret_cast<const float4*>(&sW[a * 96 + j0]);
                float4 w1 = *reinterpret_cast<const float4*>(&sW[a * 96 + j0 + 4]);
                ull wd[8] = { dup2(w0.x), dup2(w0.y), dup2(w0.z), dup2(w0.w),
                              dup2(w1.x), dup2(w1.y), dup2(w1.z), dup2(w1.w) };
                #pragma unroll
                for (int m = 0; m < 3; ++m)
                    #pragma unroll
                    for (int v = 0; v < 8; ++v) fma2(acc[m][v], am[m], wd[v]);
            }
            #pragma unroll
            for (int m = 0; m < 3; ++m) {
                float r0[8], r1[8];
                #pragma unroll
                for (int v = 0; v < 8; ++v) upk2(r0[v], r1[v], acc[m][v]);
                const float* c0a = &cL[2 * m][0].x;
                const float* c1a = &cL[2 * m + 1][0].x;
                #pragma unroll
                for (int v = 0; v < 8; ++v) {
                    const int i = i0 + 2 * m, j = j0 + v;
                    float val = r0[v] + c0a[v];
                    if (i >= j) sQ[i * 96 + j] = val;
                    if (i >  j) sQ[j * 96 + i] = val;
                }
                #pragma unroll
                for (int v = 0; v < 8; ++v) {
                    const int i = i0 + 2 * m + 1, j = j0 + v;
                    float val = r1[v] + c1a[v];
                    if (i >= j) sQ[i * 96 + j] = val;
                    if (i >  j) sQ[j * 96 + i] = val;
                }
            }
        }
        __syncthreads();

        // ---- P3: qA = c + Q@xut (0-95) | t = v - V@z (96-159) | stage sL (160-255) ----
        if (tid < NN) {
            const int i = tid;
            float cval = cg[tb * NN + i];
            float s0 = 0.f, s1 = 0.f, s2 = 0.f, s3 = 0.f;
            #pragma unroll 8
            for (int j = 0; j < 96; j += 4) {
                int j0i = j + i;     if (j0i >= 96) j0i -= 96;
                int j1i = j + 1 + i; if (j1i >= 96) j1i -= 96;
                int j2i = j + 2 + i; if (j2i >= 96) j2i -= 96;
                int j3i = j + 3 + i; if (j3i >= 96) j3i -= 96;
                s0 += sQ[i * 96 + j0i] * sxu[j0i];
                s1 += sQ[i * 96 + j1i] * sxu[j1i];
                s2 += sQ[i * 96 + j2i] * sxu[j2i];
                s3 += sQ[i * 96 + j3i] * sxu[j3i];
            }
            sq[i] = cval + (s0 + s1) + (s2 + s3);
        } else if (tid < 160) {
            const int a = tid - 96;
            const int ra = (3 * a) & 63;
            float s0 = 0.f, s1 = 0.f;
            #pragma unroll 8
            for (int j = 0; j < 64; j += 2) {
                int j0i = (j + ra) & 63;
                int j1i = (j + 1 + ra) & 63;
                s0 += sV[a * 68 + j0i] * sz[j0i];
                s1 += sV[a * 68 + j1i] * sz[j1i];
            }
            st[a] = sv[a] - s0 - s1;
        } else {
            for (int idx = tid - 160; idx < 1024; idx += 96) {
                int u = idx >> 5, c = idx & 31;
                sL[u * 33 + c] = sQ[(64 + u) * 96 + 64 + c];
            }
        }
        __syncthreads();

        // ---- P4: q += F^T t (0-95) | Cholesky + Linv (warp 4: 128-159) ----
        if (tid < NN) {
            const int i = tid;
            float f0 = 0.f, f1 = 0.f;
            #pragma unroll 8
            for (int a = 0; a < 64; a += 2) {
                f0 += sF[a * 96 + i] * st[a];
                f1 += sF[(a + 1) * 96 + i] * st[a + 1];
            }
            sq[i] += f0 + f1;
        } else if (tid >= 128 && tid < 160) {
            const int r = tid - 128;
            float Lr[32];
            #pragma unroll
            for (int kk = 0; kk < 32; ++kk) Lr[kk] = sL[r * 33 + kk];
            #pragma unroll
            for (int j = 0; j < 32; ++j) {
                float s = Lr[j];
                #pragma unroll
                for (int kk = 0; kk < j; ++kk) s -= Lr[kk] * sL[j * 33 + kk];
                float d = sqrtf(__shfl_sync(0xffffffffu, s, j));
                float val = (r == j) ? d : s / d;
                Lr[j] = val;
                if (r >= j) sL[r * 33 + j] = val;
                if (r == j) sid[j] = 1.0f / d;
                __syncwarp();
            }
            // triangular inverse: lane r computes column r of Linv
            {
                float x[32];
                #pragma unroll
                for (int j = 0; j < 32; ++j) {
                    float s = (j == r) ? 1.0f : 0.0f;
                    #pragma unroll
                    for (int kk = 0; kk < j; ++kk) s -= sL[j * 33 + kk] * x[kk];
                    x[j] = (j < r) ? 0.0f : s * sid[j];
                    sLi[j * 33 + r] = x[j];
                }
            }
        }
        __syncthreads();

        // ---- P5: Z = Linv @ [Q_ux | q_u] (tid<130) | F-prefetch 1/2 (160-255) ----
        if (tid < 130) {
            const int c  = tid % 65;
            const int r0 = (tid / 65) * 16;
            float acc[16];
            #pragma unroll
            for (int rr = 0; rr < 16; ++rr) acc[rr] = 0.f;
            #pragma unroll 4
            for (int j = 0; j < 32; ++j) {
                float rv = (c < 64) ? sQ[(64 + j) * 96 + c] : sq[64 + j];
                #pragma unroll
                for (int rr = 0; rr < 16; ++rr)
                    acc[rr] += sLi[(r0 + rr) * 33 + j] * rv;
            }
            #pragma unroll
            for (int rr = 0; rr < 16; ++rr) sZ[(r0 + rr) * 65 + c] = acc[rr];
        } else if (tid >= 160 && t > 0) {
            const float4* Fsrc = reinterpret_cast<const float4*>(
                Fg + ((size_t)(t - 1) * BATCH + b) * (NS * NN));
            float4* Fd = reinterpret_cast<float4*>(sF);
            for (int i = tid - 160; i < 768; i += 96) Fd[i] = Fsrc[i];
        }
        __syncthreads();

        // ---- P6: K = -Linv^T @ Z -> sK,gK,skv,g_k | F-prefetch 2/2 ----
        if (tid < 130) {
            const int c  = tid % 65;
            const int r0 = (tid / 65) * 16;
            float acc[16];
            #pragma unroll
            for (int rr = 0; rr < 16; ++rr) acc[rr] = 0.f;
            #pragma unroll 4
            for (int j = 0; j < 32; ++j) {
                float zv = sZ[j * 65 + c];
                #pragma unroll
                for (int rr = 0; rr < 16; ++rr)
                    acc[rr] += sLi[j * 33 + r0 + rr] * zv;
            }
            if (c < 64) {
                float* gK = g_K + tb * (NC * NS);
                #pragma unroll
                for (int rr = 0; rr < 16; ++rr) {
                    float val = -acc[rr];
                    sK[(r0 + rr) * 64 + c] = val;
                    gK[(r0 + rr) * 64 + c] = val;
                }
            } else {
                #pragma unroll
                for (int rr = 0; rr < 16; ++rr) {
                    float val = -acc[rr];
                    skv[r0 + rr] = val;
                    g_k[tb * NC + r0 + rr] = val;
                }
            }
        } else if (tid >= 160 && t > 0) {
            const float4* Fsrc = reinterpret_cast<const float4*>(
                Fg + ((size_t)(t - 1) * BATCH + b) * (NS * NN));
            float4* Fd = reinterpret_cast<float4*>(sF);
            for (int i = 768 + (tid - 160); i < 1536; i += 96) Fd[i] = Fsrc[i];
        }
        __syncthreads();

        // ---- P7: Vn = Q_xx + sym(Q_xu K) via register pair-tiles | v_new ----
        if (u7bi >= 0) {
            const int i0 = u7bi * 4, j0 = u7bj * 4;
            if (u7bi == u7bj) {
                ull acc[4][2];
                #pragma unroll
                for (int u = 0; u < 4; ++u) { acc[u][0] = 0ull; acc[u][1] = 0ull; }
                #pragma unroll 4
                for (int r = 0; r < 32; ++r) {
                    float4 qa = *reinterpret_cast<const float4*>(&sQ[(64 + r) * 96 + i0]);
                    float4 kb = *reinterpret_cast<const float4*>(&sK[r * 64 + j0]);
                    ull k0 = pk2(kb.x, kb.y), k1 = pk2(kb.z, kb.w);
                    fma2(acc[0][0], dup2(qa.x), k0); fma2(acc[0][1], dup2(qa.x), k1);
                    fma2(acc[1][0], dup2(qa.y), k0); fma2(acc[1][1], dup2(qa.y), k1);
                    fma2(acc[2][0], dup2(qa.z), k0); fma2(acc[2][1], dup2(qa.z), k1);
                    fma2(acc[3][0], dup2(qa.w), k0); fma2(acc[3][1], dup2(qa.w), k1);
                }
                float U[4][4];
                #pragma unroll
                for (int u = 0; u < 4; ++u) {
                    upk2(U[u][0], U[u][1], acc[u][0]);
                    upk2(U[u][2], U[u][3], acc[u][1]);
                }
                #pragma unroll
                for (int u = 0; u < 4; ++u)
                    #pragma unroll
                    for (int v = 0; v < 4; ++v)
                        sV[(i0 + u) * 68 + j0 + v] =
                            sQ[(i0 + u) * 96 + j0 + v] + 0.5f * (U[u][v] + U[v][u]);
            } else {
                ull accA[4][2], accB[4][2];
                #pragma unroll
                for (int u = 0; u < 4; ++u) {
                    accA[u][0] = accA[u][1] = 0ull;
                    accB[u][0] = accB[u][1] = 0ull;
                }
                #pragma unroll 2
                for (int r = 0; r < 32; ++r) {
                    float4 qi = *reinterpret_cast<const float4*>(&sQ[(64 + r) * 96 + i0]);
                    float4 qj = *reinterpret_cast<const float4*>(&sQ[(64 + r) * 96 + j0]);
                    float4 ki = *reinterpret_cast<const float4*>(&sK[r * 64 + i0]);
                    float4 kj = *reinterpret_cast<const float4*>(&sK[r * 64 + j0]);
                    ull kj0 = pk2(kj.x, kj.y), kj1 = pk2(kj.z, kj.w);
                    ull ki0 = pk2(ki.x, ki.y), ki1 = pk2(ki.z, ki.w);
                    fma2(accA[0][0], dup2(qi.x), kj0); fma2(accA[0][1], dup2(qi.x), kj1);
                    fma2(accA[1][0], dup2(qi.y), kj0); fma2(accA[1][1], dup2(qi.y), kj1);
                    fma2(accA[2][0], dup2(qi.z), kj0); fma2(accA[2][1], dup2(qi.z), kj1);
                    fma2(accA[3][0], dup2(qi.w), kj0); fma2(accA[3][1], dup2(qi.w), kj1);
                    fma2(accB[0][0], dup2(qj.x), ki0); fma2(accB[0][1], dup2(qj.x), ki1);
                    fma2(accB[1][0], dup2(qj.y), ki0); fma2(accB[1][1], dup2(qj.y), ki1);
                    fma2(accB[2][0], dup2(qj.z), ki0); fma2(accB[2][1], dup2(qj.z), ki1);
                    fma2(accB[3][0], dup2(qj.w), ki0); fma2(accB[3][1], dup2(qj.w), ki1);
                }
                float A[4][4], B[4][4];
                #pragma unroll
                for (int u = 0; u < 4; ++u) {
                    upk2(A[u][0], A[u][1], accA[u][0]);
                    upk2(A[u][2], A[u][3], accA[u][1]);
                    upk2(B[u][0], B[u][1], accB[u][0]);
                    upk2(B[u][2], B[u][3], accB[u][1]);
                }
                #pragma unroll
                for (int u = 0; u < 4; ++u)
                    #pragma unroll
                    for (int v = 0; v < 4; ++v) {
                        float val = sQ[(i0 + u) * 96 + j0 + v]
                                  + 0.5f * (A[u][v] + B[v][u]);
                        sV[(i0 + u) * 68 + j0 + v] = val;
                        sV[(j0 + v) * 68 + i0 + u] = val;
                    }
            }
        } else if (tid >= 136 && tid < 200) {
            const int i = tid - 136;
            float s = sq[i];
            #pragma unroll
            for (int r = 0; r < 32; ++r) s += sQ[(64 + r) * 96 + i] * skv[r];
            sv[i] = s;
        }
        __syncthreads();
    }

    // ================= FORWARD ROLLOUT (double-buffered) =================
    float* fx  = sm + OFF_FWD;        // x, 2 x 64
    float* fdx = fx  + 128;           // dx, 64
    float* fnu = fdx + 64;            // new_u, 32
    float* fk  = fnu + 32;            // k, 2 x 32
    float* fu  = fk  + 64;            // u, 2 x 32
    float* fxr = fu  + 64;            // xr, 2 x 64
    float* KB[2] = { sK, sZ };
    float* FB[2] = { sF, sQ };

    // preload t=0 buffers
    {
        const float4* Ks = reinterpret_cast<const float4*>(g_K + (size_t)b * (NC * NS));
        float4* Kd = reinterpret_cast<float4*>(KB[0]);
        for (int i = tid; i < 512; i += NTHR) Kd[i] = Ks[i];
        const float4* Fs = reinterpret_cast<const float4*>(Fg + (size_t)b * (NS * NN));
        float4* Fd = reinterpret_cast<float4*>(FB[0]);
        for (int i = tid; i < 1536; i += NTHR) Fd[i] = Fs[i];
        if (tid < 32) {
            fk[tid] = g_k[(size_t)b * NC + tid];
            fu[tid] = cug[(size_t)b * NC + tid];
        } else if (tid < 96) {
            int i = tid - 32;
            fxr[i] = cxg[((size_t)BATCH + b) * NS + i];   // cx[1]
        } else if (tid < 160) {
            int i = tid - 96;
            fx[i]  = x_init[(size_t)b * NS + i];
            fdx[i] = 0.f;
        }
    }
    __syncthreads();

    for (int t = 0; t < T_STEPS; ++t) {
        const int cur = t & 1, nxt = cur ^ 1;
        const size_t tb = (size_t)t * BATCH + b;

        // Phase A: new_u (0-127, quad-split) | prefetch t+1 + x output (128-255)
        if (tid < 128) {
            const int o = tid >> 2, seg = tid & 3;
            const float* Kb = KB[cur] + o * 64 + seg * 16;
            const float* dx = fdx + seg * 16;
            float s = 0.f;
            #pragma unroll
            for (int j = 0; j < 16; ++j) s += Kb[j] * dx[j];
            s += __shfl_xor_sync(0xffffffffu, s, 1);
            s += __shfl_xor_sync(0xffffffffu, s, 2);
            if (seg == 0) {
                float nu = s + fk[cur * 32 + o] + fu[cur * 32 + o];
                fnu[o] = nu;
                out[(size_t)T_STEPS * BATCH * NS + tb * NC + o] = nu;
            }
        } else {
            const int idx = tid - 128;
            if (idx < 64) out[tb * NS + idx] = fx[cur * 64 + idx];
            if (t + 1 < T_STEPS) {
                const size_t tb2 = tb + BATCH;
                const float4* Ks = reinterpret_cast<const float4*>(g_K + tb2 * (NC * NS));
                float4* Kd = reinterpret_cast<float4*>(KB[nxt]);
                for (int i = idx; i < 512; i += 128) Kd[i] = Ks[i];
                const float4* Fs = reinterpret_cast<const float4*>(Fg + tb2 * (NS * NN));
                float4* Fd = reinterpret_cast<float4*>(FB[nxt]);
                for (int i = idx; i < 1536; i += 128) Fd[i] = Fs[i];
                if (idx < 32) {
                    fk[nxt * 32 + idx] = g_k[tb2 * NC + idx];
                    fu[nxt * 32 + idx] = cug[tb2 * NC + idx];
                } else if (idx < 96) {
                    int i = idx - 32;
                    fxr[nxt * 64 + i] = (t + 2 < T_STEPS)
                        ? cxg[(tb2 + BATCH) * NS + i] : 0.f;
                }
            }
        }
        __syncthreads();

        // Phase B: x_next = F @ [x; new_u] (all 256, quad-split 24)
        {
            const int o = tid >> 2, seg = tid & 3;
            const float* Fr = FB[cur] + o * 96 + seg * 24;
            float s = 0.f;
            #pragma unroll
            for (int j = 0; j < 24; ++j) {
                int jj = seg * 24 + j;
                float xv = (jj < 64) ? fx[cur * 64 + jj] : fnu[jj - 64];
                s += Fr[j] * xv;
            }
            s += __shfl_xor_sync(0xffffffffu, s, 1);
            s += __shfl_xor_sync(0xffffffffu, s, 2);
            if (seg == 0) {
                fx[nxt * 64 + o] = s;
                fdx[o] = s - fxr[cur * 64 + o];
            }
        }
        __syncthreads();
    }
}

extern "C" void kernel_launch(void* const* d_in, const int* in_sizes, int n_in,
                              void* d_out, int out_size)
{
    const float* x_init = (const float*)d_in[0];
    const float* C      = (const float*)d_in[1];
    const float* c      = (const float*)d_in[2];
    const float* F      = (const float*)d_in[3];
    const float* cx     = (const float*)d_in[4];
    const float* cu     = (const float*)d_in[5];

    cudaFuncSetAttribute(lqr_kernel,
                         cudaFuncAttributeMaxDynamicSharedMemorySize, SMEM_BYTES);
    lqr_kernel<<<BATCH, NTHR, SMEM_BYTES>>>(x_init, C, c, F, cx, cu, (float*)d_out);
}

// round 7
// speedup vs baseline: 1.7236x; 1.0084x over previous
#include <cuda_runtime.h>

#define T_STEPS 50
#define BATCH   256
#define NS      64
#define NC      32
#define NN      96
#define NTHR    256

typedef unsigned long long ull;

__device__ float g_K[(size_t)T_STEPS * BATCH * NC * NS];   // [t][b][32][64]
__device__ float g_k[(size_t)T_STEPS * BATCH * NC];        // [t][b][32]

// ---- shared memory layout (floats) ----
#define OFF_V    0                       // V carry, 64 x 68 (symmetric)
#define OFF_F    (OFF_V  + 64*68)        // F tile, 64 x 96
#define OFF_Q    (OFF_F  + 6144)         // Q, 96 x 96 FULL (mirrored)
#define OFF_WB   (OFF_Q  + 9216)         // W (64x96) -- dead after phase 2
#define OFF_LI   (OFF_WB)                // Linv 32x33       (overlaps W)
#define OFF_Z    (OFF_LI + 1056)         // Z 32x65          (overlaps W)
#define OFF_K    (OFF_Z  + 2080)         // K 32x64          (overlaps W)
#define OFF_v    (OFF_WB + 6144)         // v carry, 64
#define OFF_q    (OFF_v  + 64)           // q, 96
#define OFF_xu   (OFF_q  + 96)           // xut, 96
#define OFF_kv   (OFF_xu + 96)           // k vec, 32
#define OFF_T    (OFF_kv + 32)           // t = v - V z, 64
#define OFF_id   (OFF_T  + 64)           // inv diag, 32
#define OFF_zv   (OFF_id + 32)           // z = F xut, 64
#define OFF_L    (OFF_zv + 64)           // Cholesky 32x33 (DEDICATED)
#define OFF_FWD  (OFF_L  + 1056)         // forward-pass arrays (480)
#define SMEM_FLOATS (OFF_FWD + 480)
#define SMEM_BYTES  (SMEM_FLOATS * 4)

// ---- packed fp32x2 helpers (SASS FFMA2 path) ----
__device__ __forceinline__ ull pk2(float lo, float hi) {
    ull r; asm("mov.b64 %0, {%1, %2};" : "=l"(r) : "f"(lo), "f"(hi)); return r;
}
__device__ __forceinline__ ull dup2(float x) { return pk2(x, x); }
__device__ __forceinline__ void upk2(float& lo, float& hi, ull v) {
    asm("mov.b64 {%0, %1}, %2;" : "=f"(lo), "=f"(hi) : "l"(v));
}
__device__ __forceinline__ void fma2(ull& d, ull a, ull b) {
    asm("fma.rn.f32x2 %0, %2, %3, %1;" : "=l"(d) : "l"(d), "l"(a), "l"(b));
}

__global__ __launch_bounds__(NTHR, 2)
void lqr_kernel(const float* __restrict__ x_init,
                const float* __restrict__ Cg,
                const float* __restrict__ cg,
                const float* __restrict__ Fg,
                const float* __restrict__ cxg,
                const float* __restrict__ cug,
                float* __restrict__ out)
{
    extern __shared__ float sm[];
    const int b   = blockIdx.x;
    const int tid = threadIdx.x;

    float* sV  = sm + OFF_V;
    float* sF  = sm + OFF_F;
    float* sQ  = sm + OFF_Q;
    float* sW  = sm + OFF_WB;
    float* sLi = sm + OFF_LI;
    float* sZ  = sm + OFF_Z;
    float* sK  = sm + OFF_K;
    float* sv  = sm + OFF_v;
    float* sq  = sm + OFF_q;
    float* sxu = sm + OFF_xu;
    float* skv = sm + OFF_kv;
    float* st  = sm + OFF_T;
    float* sid = sm + OFF_id;
    float* sz  = sm + OFF_zv;
    float* sL  = sm + OFF_L;

    // Phase-2 job map: 6x8 tiles over 96x96, lower blocks (6bi+5 >= 8bj): 108 jobs.
    int p2bi = -1, p2bj = 0;
    {
        int idx = tid;
        #pragma unroll
        for (int r = 0; r < 16; ++r) {
            int cnt = (6 * r + 5) / 8 + 1;
            if (idx < cnt && p2bi < 0) { p2bi = r; p2bj = idx; }
            if (p2bi < 0) idx -= cnt;
        }
    }
    const bool p2a = (p2bi >= 0);

    // Phase-6 pair-tile map: 4x4 tiles on 64x64, (bi>=bj): 136 jobs.
    int u7bi = -1, u7bj = 0;
    {
        int idx = tid;
        #pragma unroll
        for (int r = 0; r < 16; ++r) {
            int cnt = r + 1;
            if (idx < cnt && u7bi < 0) { u7bi = r; u7bj = idx; }
            if (u7bi < 0) idx -= cnt;
        }
    }

    // ---------------- init ----------------
    for (int i = tid; i < 64 * 68; i += NTHR) sV[i] = 0.f;
    if (tid < NS) sv[tid] = 0.f;
    {
        const float* Fsrc = Fg + ((size_t)(T_STEPS - 1) * BATCH + b) * (NS * NN);
        for (int i = tid; i < NS * NN; i += NTHR) sF[i] = Fsrc[i];
    }
    __syncthreads();

    // ================= BACKWARD RICCATI SCAN =================
    for (int t = T_STEPS - 1; t >= 0; --t) {
        const size_t tb = (size_t)t * BATCH + b;

        // ---- P1: W = V @ F (64x96), 4x12 FFMA2 tiles (tid<128)
        //      | xut -> z = F@xut -> t = v - V@z  (tid>=128, internal bars) ----
        if (tid < 128) {
            const int i0 = (tid >> 3) * 4;      // 16 row-blocks
            const int j0 = (tid & 7) * 12;      // 8 col-blocks
            ull acc[4][6];
            #pragma unroll
            for (int u = 0; u < 4; ++u)
                #pragma unroll
                for (int p = 0; p < 6; ++p) acc[u][p] = 0ull;
            #pragma unroll 2
            for (int a = 0; a < 64; ++a) {
                float4 b0 = *reinterpret_cast<const float4*>(&sF[a * 96 + j0]);
                float4 b1 = *reinterpret_cast<const float4*>(&sF[a * 96 + j0 + 4]);
                float4 b2 = *reinterpret_cast<const float4*>(&sF[a * 96 + j0 + 8]);
                ull bv[6] = { pk2(b0.x, b0.y), pk2(b0.z, b0.w),
                              pk2(b1.x, b1.y), pk2(b1.z, b1.w),
                              pk2(b2.x, b2.y), pk2(b2.z, b2.w) };
                float4 av = *reinterpret_cast<const float4*>(&sV[a * 68 + i0]); // V sym
                ull a0 = dup2(av.x), a1 = dup2(av.y), a2 = dup2(av.z), a3 = dup2(av.w);
                #pragma unroll
                for (int p = 0; p < 6; ++p) {
                    fma2(acc[0][p], a0, bv[p]); fma2(acc[1][p], a1, bv[p]);
                    fma2(acc[2][p], a2, bv[p]); fma2(acc[3][p], a3, bv[p]);
                }
            }
            #pragma unroll
            for (int u = 0; u < 4; ++u)
                #pragma unroll
                for (int p = 0; p < 6; ++p)
                    *reinterpret_cast<ull*>(&sW[(i0 + u) * 96 + j0 + 2 * p]) = acc[u][p];
        } else {
            const int idx = tid - 128;
            if (idx < NS)            sxu[idx] = cxg[tb * NS + idx];
            else if (idx < NN)       sxu[idx] = cug[tb * NC + (idx - NS)];
            asm volatile("bar.sync 3, 128;" ::: "memory");   // warps 4-7 only
            if (idx < 64) {
                const int o = idx;
                int ro = (3 * o) % 96;
                float s0 = 0.f, s1 = 0.f;
                #pragma unroll 8
                for (int j = 0; j < 96; j += 2) {
                    int j0i = j + ro;     if (j0i >= 96) j0i -= 96;
                    int j1i = j + 1 + ro; if (j1i >= 96) j1i -= 96;
                    s0 += sF[o * 96 + j0i] * sxu[j0i];
                    s1 += sF[o * 96 + j1i] * sxu[j1i];
                }
                sz[o] = s0 + s1;
            }
            asm volatile("bar.sync 3, 128;" ::: "memory");
            if (idx < 64) {
                const int a = idx;
                const int ra = (3 * a) & 63;
                float s0 = 0.f, s1 = 0.f;
                #pragma unroll 8
                for (int j = 0; j < 64; j += 2) {
                    int j0i = (j + ra) & 63;
                    int j1i = (j + 1 + ra) & 63;
                    s0 += sV[a * 68 + j0i] * sz[j0i];
                    s1 += sV[a * 68 + j1i] * sz[j1i];
                }
                st[a] = sv[a] - s0 - s1;
            }
        }
        __syncthreads();

        // ---- P2: Q = C + F^T W (lower 6x8 + mirror), dual-write Quu -> sL ----
        if (p2a) {
            const int i0 = p2bi * 6, j0 = p2bj * 8;
            const float* Crow = Cg + tb * (NN * NN);
            float4 cL[6][2];
            #pragma unroll
            for (int r = 0; r < 6; ++r) {
                cL[r][0] = *reinterpret_cast<const float4*>(&Crow[(i0 + r) * 96 + j0]);
                cL[r][1] = *reinterpret_cast<const float4*>(&Crow[(i0 + r) * 96 + j0 + 4]);
            }
            ull acc[3][8];
            #pragma unroll
            for (int m = 0; m < 3; ++m)
                #pragma unroll
                for (int v = 0; v < 8; ++v) acc[m][v] = 0ull;
            #pragma unroll 2
            for (int a = 0; a < 64; ++a) {
                ull am[3];
                #pragma unroll
                for (int m = 0; m < 3; ++m)
                    am[m] = *reinterpret_cast<const ull*>(&sF[a * 96 + i0 + 2 * m]);
                float4 w0 = *reinterpret_cast<const float4*>(&sW[a * 96 + j0]);
                float4 w1 = *reinterpret_cast<const float4*>(&sW[a * 96 + j0 + 4]);
                ull wd[8] = { dup2(w0.x), dup2(w0.y), dup2(w0.z), dup2(w0.w),
                              dup2(w1.x), dup2(w1.y), dup2(w1.z), dup2(w1.w) };
                #pragma unroll
                for (int m = 0; m < 3; ++m)
                    #pragma unroll
                    for (int v = 0; v < 8; ++v) fma2(acc[m][v], am[m], wd[v]);
            }
            #pragma unroll
            for (int m = 0; m < 3; ++m) {
                float r0[8], r1[8];
                #pragma unroll
                for (int v = 0; v < 8; ++v) upk2(r0[v], r1[v], acc[m][v]);
                const float* c0a = &cL[2 * m][0].x;
                const float* c1a = &cL[2 * m + 1][0].x;
                #pragma unroll
                for (int v = 0; v < 8; ++v) {
                    const int i = i0 + 2 * m, j = j0 + v;
                    float val = r0[v] + c0a[v];
                    if (i >= j) {
                        sQ[i * 96 + j] = val;
                        if (j >= 64) sL[(i - 64) * 33 + (j - 64)] = val;
                    }
                    if (i > j) {
                        sQ[j * 96 + i] = val;
                        if (j >= 64) sL[(j - 64) * 33 + (i - 64)] = val;
                    }
                }
                #pragma unroll
                for (int v = 0; v < 8; ++v) {
                    const int i = i0 + 2 * m + 1, j = j0 + v;
                    float val = r1[v] + c1a[v];
                    if (i >= j) {
                        sQ[i * 96 + j] = val;
                        if (j >= 64) sL[(i - 64) * 33 + (j - 64)] = val;
                    }
                    if (i > j) {
                        sQ[j * 96 + i] = val;
                        if (j >= 64) sL[(j - 64) * 33 + (i - 64)] = val;
                    }
                }
            }
        }
        __syncthreads();

        // ---- P3: q = c + Q@xut + F^T t (0-95) | Cholesky + Linv (warp 4) ----
        if (tid < NN) {
            const int i = tid;
            float cval = cg[tb * NN + i];
            float s0 = 0.f, s1 = 0.f, s2 = 0.f, s3 = 0.f;
            #pragma unroll 8
            for (int j = 0; j < 96; j += 4) {
                int j0i = j + i;     if (j0i >= 96) j0i -= 96;
                int j1i = j + 1 + i; if (j1i >= 96) j1i -= 96;
                int j2i = j + 2 + i; if (j2i >= 96) j2i -= 96;
                int j3i = j + 3 + i; if (j3i >= 96) j3i -= 96;
                s0 += sQ[i * 96 + j0i] * sxu[j0i];
                s1 += sQ[i * 96 + j1i] * sxu[j1i];
                s2 += sQ[i * 96 + j2i] * sxu[j2i];
                s3 += sQ[i * 96 + j3i] * sxu[j3i];
            }
            float f0 = 0.f, f1 = 0.f;
            #pragma unroll 8
            for (int a = 0; a < 64; a += 2) {
                f0 += sF[a * 96 + i] * st[a];
                f1 += sF[(a + 1) * 96 + i] * st[a + 1];
            }
            sq[i] = cval + (s0 + s1) + (s2 + s3) + (f0 + f1);
        } else if (tid >= 128 && tid < 160) {
            const int r = tid - 128;
            float Lr[32];
            #pragma unroll
            for (int kk = 0; kk < 32; ++kk) Lr[kk] = sL[r * 33 + kk];
            #pragma unroll
            for (int j = 0; j < 32; ++j) {
                float s = Lr[j];
                #pragma unroll
                for (int kk = 0; kk < j; ++kk) s -= Lr[kk] * sL[j * 33 + kk];
                float d = sqrtf(__shfl_sync(0xffffffffu, s, j));
                float val = (r == j) ? d : s / d;
                Lr[j] = val;
                if (r >= j) sL[r * 33 + j] = val;
                if (r == j) sid[j] = 1.0f / d;
                __syncwarp();
            }
            // triangular inverse: lane r computes column r of Linv
            {
                float x[32];
                #pragma unroll
                for (int j = 0; j < 32; ++j) {
                    float s = (j == r) ? 1.0f : 0.0f;
                    #pragma unroll
                    for (int kk = 0; kk < j; ++kk) s -= sL[j * 33 + kk] * x[kk];
                    x[j] = (j < r) ? 0.0f : s * sid[j];
                    sLi[j * 33 + r] = x[j];
                }
            }
        }
        __syncthreads();

        // ---- P4: Z = Linv @ [Q_ux | q_u] (tid<130) | F-prefetch 1/2 (160-255) ----
        if (tid < 130) {
            const int c  = tid % 65;
            const int r0 = (tid / 65) * 16;
            float acc[16];
            #pragma unroll
            for (int rr = 0; rr < 16; ++rr) acc[rr] = 0.f;
            #pragma unroll 4
            for (int j = 0; j < 32; ++j) {
                float rv = (c < 64) ? sQ[(64 + j) * 96 + c] : sq[64 + j];
                #pragma unroll
                for (int rr = 0; rr < 16; ++rr)
                    acc[rr] += sLi[(r0 + rr) * 33 + j] * rv;
            }
            #pragma unroll
            for (int rr = 0; rr < 16; ++rr) sZ[(r0 + rr) * 65 + c] = acc[rr];
        } else if (tid >= 160 && t > 0) {
            const float4* Fsrc = reinterpret_cast<const float4*>(
                Fg + ((size_t)(t - 1) * BATCH + b) * (NS * NN));
            float4* Fd = reinterpret_cast<float4*>(sF);
            for (int i = tid - 160; i < 768; i += 96) Fd[i] = Fsrc[i];
        }
        __syncthreads();

        // ---- P5: K = -Linv^T @ Z -> sK,gK,skv,g_k | F-prefetch 2/2 ----
        if (tid < 130) {
            const int c  = tid % 65;
            const int r0 = (tid / 65) * 16;
            float acc[16];
            #pragma unroll
            for (int rr = 0; rr < 16; ++rr) acc[rr] = 0.f;
            #pragma unroll 4
            for (int j = 0; j < 32; ++j) {
                float zv = sZ[j * 65 + c];
                #pragma unroll
                for (int rr = 0; rr < 16; ++rr)
                    acc[rr] += sLi[j * 33 + r0 + rr] * zv;
            }
            if (c < 64) {
                float* gK = g_K + tb * (NC * NS);
                #pragma unroll
                for (int rr = 0; rr < 16; ++rr) {
                    float val = -acc[rr];
                    sK[(r0 + rr) * 64 + c] = val;
                    gK[(r0 + rr) * 64 + c] = val;
                }
            } else {
                #pragma unroll
                for (int rr = 0; rr < 16; ++rr) {
                    float val = -acc[rr];
                    skv[r0 + rr] = val;
                    g_k[tb * NC + r0 + rr] = val;
                }
            }
        } else if (tid >= 160 && t > 0) {
            const float4* Fsrc = reinterpret_cast<const float4*>(
                Fg + ((size_t)(t - 1) * BATCH + b) * (NS * NN));
            float4* Fd = reinterpret_cast<float4*>(sF);
            for (int i = 768 + (tid - 160); i < 1536; i += 96) Fd[i] = Fsrc[i];
        }
        __syncthreads();

        // ---- P6: Vn = Q_xx + sym(Q_xu K) via register pair-tiles | v_new ----
        if (u7bi >= 0) {
            const int i0 = u7bi * 4, j0 = u7bj * 4;
            if (u7bi == u7bj) {
                ull acc[4][2];
                #pragma unroll
                for (int u = 0; u < 4; ++u) { acc[u][0] = 0ull; acc[u][1] = 0ull; }
                #pragma unroll 4
                for (int r = 0; r < 32; ++r) {
                    float4 qa = *reinterpret_cast<const float4*>(&sQ[(64 + r) * 96 + i0]);
                    float4 kb = *reinterpret_cast<const float4*>(&sK[r * 64 + j0]);
                    ull k0 = pk2(kb.x, kb.y), k1 = pk2(kb.z, kb.w);
                    fma2(acc[0][0], dup2(qa.x), k0); fma2(acc[0][1], dup2(qa.x), k1);
                    fma2(acc[1][0], dup2(qa.y), k0); fma2(acc[1][1], dup2(qa.y), k1);
                    fma2(acc[2][0], dup2(qa.z), k0); fma2(acc[2][1], dup2(qa.z), k1);
                    fma2(acc[3][0], dup2(qa.w), k0); fma2(acc[3][1], dup2(qa.w), k1);
                }
                float U[4][4];
                #pragma unroll
                for (int u = 0; u < 4; ++u) {
                    upk2(U[u][0], U[u][1], acc[u][0]);
                    upk2(U[u][2], U[u][3], acc[u][1]);
                }
                #pragma unroll
                for (int u = 0; u < 4; ++u)
                    #pragma unroll
                    for (int v = 0; v < 4; ++v)
                        sV[(i0 + u) * 68 + j0 + v] =
                            sQ[(i0 + u) * 96 + j0 + v] + 0.5f * (U[u][v] + U[v][u]);
            } else {
                ull accA[4][2], accB[4][2];
                #pragma unroll
                for (int u = 0; u < 4; ++u) {
                    accA[u][0] = accA[u][1] = 0ull;
                    accB[u][0] = accB[u][1] = 0ull;
                }
                #pragma unroll 2
                for (int r = 0; r < 32; ++r) {
                    float4 qi = *reinterpret_cast<const float4*>(&sQ[(64 + r) * 96 + i0]);
                    float4 qj = *reinterpret_cast<const float4*>(&sQ[(64 + r) * 96 + j0]);
                    float4 ki = *reinterpret_cast<const float4*>(&sK[r * 64 + i0]);
                    float4 kj = *reinterpret_cast<const float4*>(&sK[r * 64 + j0]);
                    ull kj0 = pk2(kj.x, kj.y), kj1 = pk2(kj.z, kj.w);
                    ull ki0 = pk2(ki.x, ki.y), ki1 = pk2(ki.z, ki.w);
                    fma2(accA[0][0], dup2(qi.x), kj0); fma2(accA[0][1], dup2(qi.x), kj1);
                    fma2(accA[1][0], dup2(qi.y), kj0); fma2(accA[1][1], dup2(qi.y), kj1);
                    fma2(accA[2][0], dup2(qi.z), kj0); fma2(accA[2][1], dup2(qi.z), kj1);
                    fma2(accA[3][0], dup2(qi.w), kj0); fma2(accA[3][1], dup2(qi.w), kj1);
                    fma2(accB[0][0], dup2(qj.x), ki0); fma2(accB[0][1], dup2(qj.x), ki1);
                    fma2(accB[1][0], dup2(qj.y), ki0); fma2(accB[1][1], dup2(qj.y), ki1);
                    fma2(accB[2][0], dup2(qj.z), ki0); fma2(accB[2][1], dup2(qj.z), ki1);
                    fma2(accB[3][0], dup2(qj.w), ki0); fma2(accB[3][1], dup2(qj.w), ki1);
                }
                float A[4][4], B[4][4];
                #pragma unroll
                for (int u = 0; u < 4; ++u) {
                    upk2(A[u][0], A[u][1], accA[u][0]);
                    upk2(A[u][2], A[u][3], accA[u][1]);
                    upk2(B[u][0], B[u][1], accB[u][0]);
                    upk2(B[u][2], B[u][3], accB[u][1]);
                }
                #pragma unroll
                for (int u = 0; u < 4; ++u)
                    #pragma unroll
                    for (int v = 0; v < 4; ++v) {
                        float val = sQ[(i0 + u) * 96 + j0 + v]
                                  + 0.5f * (A[u][v] + B[v][u]);
                        sV[(i0 + u) * 68 + j0 + v] = val;
                        sV[(j0 + v) * 68 + i0 + u] = val;
                    }
            }
        } else if (tid >= 136 && tid < 200) {
            const int i = tid - 136;
            float s = sq[i];
            #pragma unroll
            for (int r = 0; r < 32; ++r) s += sQ[(64 + r) * 96 + i] * skv[r];
            sv[i] = s;
        }
        __syncthreads();
    }

    // ================= FORWARD ROLLOUT (double-buffered) =================
    float* fx  = sm + OFF_FWD;        // x, 2 x 64
    float* fdx = fx  + 128;           // dx, 64
    float* fnu = fdx + 64;            // new_u, 32
    float* fk  = fnu + 32;            // k, 2 x 32
    float* fu  = fk  + 64;            // u, 2 x 32
    float* fxr = fu  + 64;            // xr, 2 x 64
    float* KB[2] = { sK, sZ };
    float* FB[2] = { sF, sQ };

    // preload t=0 buffers
    {
        const float4* Ks = reinterpret_cast<const float4*>(g_K + (size_t)b * (NC * NS));
        float4* Kd = reinterpret_cast<float4*>(KB[0]);
        for (int i = tid; i < 512; i += NTHR) Kd[i] = Ks[i];
        const float4* Fs = reinterpret_cast<const float4*>(Fg + (size_t)b * (NS * NN));
        float4* Fd = reinterpret_cast<float4*>(FB[0]);
        for (int i = tid; i < 1536; i += NTHR) Fd[i] = Fs[i];
        if (tid < 32) {
            fk[tid] = g_k[(size_t)b * NC + tid];
            fu[tid] = cug[(size_t)b * NC + tid];
        } else if (tid < 96) {
            int i = tid - 32;
            fxr[i] = cxg[((size_t)BATCH + b) * NS + i];   // cx[1]
        } else if (tid < 160) {
            int i = tid - 96;
            fx[i]  = x_init[(size_t)b * NS + i];
            fdx[i] = 0.f;
        }
    }
    __syncthreads();

    for (int t = 0; t < T_STEPS; ++t) {
        const int cur = t & 1, nxt = cur ^ 1;
        const size_t tb = (size_t)t * BATCH + b;

        // Phase A: new_u (0-127, quad-split) | prefetch t+1 + x output (128-255)
        if (tid < 128) {
            const int o = tid >> 2, seg = tid & 3;
            const float* Kb = KB[cur] + o * 64 + seg * 16;
            const float* dx = fdx + seg * 16;
            float s = 0.f;
            #pragma unroll
            for (int j = 0; j < 16; ++j) s += Kb[j] * dx[j];
            s += __shfl_xor_sync(0xffffffffu, s, 1);
            s += __shfl_xor_sync(0xffffffffu, s, 2);
            if (seg == 0) {
                float nu = s + fk[cur * 32 + o] + fu[cur * 32 + o];
                fnu[o] = nu;
                out[(size_t)T_STEPS * BATCH * NS + tb * NC + o] = nu;
            }
        } else {
            const int idx = tid - 128;
            if (idx < 64) out[tb * NS + idx] = fx[cur * 64 + idx];
            if (t + 1 < T_STEPS) {
                const size_t tb2 = tb + BATCH;
                const float4* Ks = reinterpret_cast<const float4*>(g_K + tb2 * (NC * NS));
                float4* Kd = reinterpret_cast<float4*>(KB[nxt]);
                for (int i = idx; i < 512; i += 128) Kd[i] = Ks[i];
                const float4* Fs = reinterpret_cast<const float4*>(Fg + tb2 * (NS * NN));
                float4* Fd = reinterpret_cast<float4*>(FB[nxt]);
                for (int i = idx; i < 1536; i += 128) Fd[i] = Fs[i];
                if (idx < 32) {
                    fk[nxt * 32 + idx] = g_k[tb2 * NC + idx];
                    fu[nxt * 32 + idx] = cug[tb2 * NC + idx];
                } else if (idx < 96) {
                    int i = idx - 32;
                    fxr[nxt * 64 + i] = (t + 2 < T_STEPS)
                        ? cxg[(tb2 + BATCH) * NS + i] : 0.f;
                }
            }
        }
        __syncthreads();

        // Phase B: x_next = F @ [x; new_u] (all 256, quad-split 24)
        {
            const int o = tid >> 2, seg = tid & 3;
            const float* Fr = FB[cur] + o * 96 + seg * 24;
            float s = 0.f;
            #pragma unroll
            for (int j = 0; j < 24; ++j) {
                int jj = seg * 24 + j;
                float xv = (jj < 64) ? fx[cur * 64 + jj] : fnu[jj - 64];
                s += Fr[j] * xv;
            }
            s += __shfl_xor_sync(0xffffffffu, s, 1);
            s += __shfl_xor_sync(0xffffffffu, s, 2);
            if (seg == 0) {
                fx[nxt * 64 + o] = s;
                fdx[o] = s - fxr[cur * 64 + o];
            }
        }
        __syncthreads();
    }
}

extern "C" void kernel_launch(void* const* d_in, const int* in_sizes, int n_in,
                              void* d_out, int out_size)
{
    const float* x_init = (const float*)d_in[0];
    const float* C      = (const float*)d_in[1];
    const float* c      = (const float*)d_in[2];
    const float* F      = (const float*)d_in[3];
    const float* cx     = (const float*)d_in[4];
    const float* cu     = (const float*)d_in[5];

    cudaFuncSetAttribute(lqr_kernel,
                         cudaFuncAttributeMaxDynamicSharedMemorySize, SMEM_BYTES);
    lqr_kernel<<<BATCH, NTHR, SMEM_BYTES>>>(x_init, C, c, F, cx, cu, (float*)d_out);
}